// round 14
// baseline (speedup 1.0000x reference)
#include <cuda_runtime.h>
#include <cuda_bf16.h>
#include <math.h>
#include <stdint.h>

#define TT   1536
#define CDIM 1536
#define HH   8
#define KD   64
#define VD   192
#define RD   3071
#define RDP  3072
#define NB   32

typedef __nv_bfloat16 bf16;

// ========================= helpers =========================
__device__ __forceinline__ uint32_t smem_to_u32(const void* p) {
    uint32_t a;
    asm("{ .reg .u64 t; cvta.to.shared.u64 t, %1; cvt.u32.u64 %0, t; }" : "=r"(a) : "l"(p));
    return a;
}
#define CP_ASYNC16(dst, src) \
    asm volatile("cp.async.cg.shared.global [%0], [%1], 16;" :: "r"(dst), "l"(src))
#define CP_COMMIT() asm volatile("cp.async.commit_group;" ::: "memory")
#define CP_WAIT2()  asm volatile("cp.async.wait_group 2;" ::: "memory")

__device__ __forceinline__ void ldm_x4(uint32_t* r, uint32_t addr) {
    asm volatile("ldmatrix.sync.aligned.m8n8.x4.shared.b16 {%0,%1,%2,%3}, [%4];"
        : "=r"(r[0]), "=r"(r[1]), "=r"(r[2]), "=r"(r[3]) : "r"(addr));
}
__device__ __forceinline__ void mma_bf16(float* c, const uint32_t* a, const uint32_t* b) {
    asm volatile("mma.sync.aligned.m16n8k16.row.col.f32.bf16.bf16.f32 "
        "{%0,%1,%2,%3}, {%4,%5,%6,%7}, {%8,%9}, {%0,%1,%2,%3};"
        : "+f"(c[0]), "+f"(c[1]), "+f"(c[2]), "+f"(c[3])
        : "r"(a[0]), "r"(a[1]), "r"(a[2]), "r"(a[3]), "r"(b[0]), "r"(b[1]));
}

// ========================= scratch =========================
__device__ float g_gprobs[RD * NB];
__device__ float g_gmax;
__device__ __align__(16) bf16 g_pe_hi[RDP * 192], g_pe_lo[RDP * 192];
__device__ __align__(16) bf16 g_wqkT_hi[1024 * CDIM], g_wqkT_lo[1024 * CDIM];
__device__ __align__(16) bf16 g_wvT_hi[CDIM * CDIM], g_wvT_lo[CDIM * CDIM];
__device__ __align__(16) bf16 g_weT_hi[CDIM * CDIM], g_weT_lo[CDIM * CDIM];
__device__ __align__(16) bf16 g_wrkT_hi[512 * 192], g_wrkT_lo[512 * 192];
__device__ __align__(16) bf16 g_in_hi[TT * CDIM], g_in_lo[TT * CDIM];
__device__ __align__(16) float g_qk[2 * HH * TT * KD];   // heads 0-7: q (pre-scaled), 8-15: k
__device__ __align__(16) float g_v[HH * TT * VD];
__device__ __align__(16) float g_rkf[HH * RDP * KD];
__device__ __align__(16) bf16 g_qw_hi[HH * TT * KD], g_qw_lo[HH * TT * KD];
__device__ __align__(16) bf16 g_qr_hi[HH * TT * KD], g_qr_lo[HH * TT * KD];
__device__ __align__(16) bf16 g_k_hi[HH * TT * KD], g_k_lo[HH * TT * KD];
__device__ __align__(16) bf16 g_rk_hi[HH * RDP * KD], g_rk_lo[HH * RDP * KD];
__device__ __align__(16) bf16 g_vT_hi[HH * VD * TT], g_vT_lo[HH * VD * TT];
__device__ __align__(16) float g_content[(size_t)HH * TT * TT];
__device__ __align__(16) float g_rel[(size_t)HH * TT * RDP];
__device__ __align__(16) bf16 g_p_hi[(size_t)HH * TT * TT], g_p_lo[(size_t)HH * TT * TT];
__device__ __align__(16) bf16 g_at_hi[TT * CDIM], g_at_lo[TT * CDIM];

__device__ __forceinline__ void split2(float x, bf16* hi, bf16* lo) {
    bf16 h = __float2bfloat16(x);
    *hi = h;
    *lo = __float2bfloat16(x - __bfloat162float(h));
}

// ========================= positional features =========================
__global__ void pf_gamma_raw_kernel() {
    int idx = blockIdx.x * blockDim.x + threadIdx.x;
    if (idx >= RD * NB) return;
    int r = idx / NB, i = idx % NB;
    double x    = fabs((double)(r - (TT - 1)));
    double mean = 48.0 * (i + 1);
    double conc = (mean / 24.0) * (mean / 24.0);
    double rate = mean / 576.0;
    double lu   = (conc - 1.0) * log(x) - rate * x;
    double ln   = lgamma(conc) - conc * log(rate);
    g_gprobs[idx] = (float)exp(lu - ln) + 1e-8f;
}

__global__ void pf_max_kernel() {
    __shared__ float s[1024];
    int t = threadIdx.x;
    float m = 0.f;
    for (int i = t; i < RD * NB; i += 1024) m = fmaxf(m, g_gprobs[i]);
    s[t] = m; __syncthreads();
    for (int o = 512; o > 0; o >>= 1) { if (t < o) s[t] = fmaxf(s[t], s[t + o]); __syncthreads(); }
    if (t == 0) g_gmax = s[0];
}

__global__ void pf_build_kernel() {
    int idx = blockIdx.x * blockDim.x + threadIdx.x;
    if (idx >= RDP * 96) return;
    int r = idx / 96, i = idx % 96;
    float v1 = 0.f, v2 = 0.f;
    if (r < RD) {
        float p  = (float)(r - (TT - 1));
        float ap = fabsf(p);
        float val;
        if (i < 32) {
            double mr = log(1536.0) / log(2.0);
            double hl = pow(2.0, 3.0 + (double)i * (mr - 3.0) / 31.0);
            val = expf(-(float)(0.6931471805599453 / hl) * ap);
        } else if (i < 64) {
            float cw = exp2f((float)(i - 32 + 1)) - 1.0f;
            val = (cw > ap) ? 1.0f : 0.0f;
        } else {
            val = g_gprobs[r * NB + (i - 64)] / g_gmax;
        }
        float sg = (p > 0.f) ? 1.f : ((p < 0.f) ? -1.f : 0.f);
        v1 = val; v2 = sg * val;
    }
    split2(v1, &g_pe_hi[r * 192 + i],      &g_pe_lo[r * 192 + i]);
    split2(v2, &g_pe_hi[r * 192 + 96 + i], &g_pe_lo[r * 192 + 96 + i]);
}

// ========================= fused prep: input split + all weight transpose-splits =========================
// blocks [0,2304): Wv  | [2304,3072): Wq (scale 1/8) | [3072,3840): Wk | [3840,6144): We
// [6144,6240): Wrk | [6240,8544): input split (float4 path)
__global__ void prep_kernel(const float* __restrict__ inputs,
                            const float* __restrict__ Wq, const float* __restrict__ Wk,
                            const float* __restrict__ Wv, const float* __restrict__ We,
                            const float* __restrict__ Wrk) {
    __shared__ float t[32][33];
    int b = blockIdx.x;
    int tid = threadIdx.x;
    if (b >= 6240) {
        int i = (b - 6240) * 256 + tid;
        float4 v = reinterpret_cast<const float4*>(inputs)[i];
        bf16 h0, l0, h1, l1, h2, l2, h3, l3;
        split2(v.x, &h0, &l0); split2(v.y, &h1, &l1);
        split2(v.z, &h2, &l2); split2(v.w, &h3, &l3);
        __nv_bfloat162* hp = reinterpret_cast<__nv_bfloat162*>(g_in_hi + 4 * (size_t)i);
        __nv_bfloat162* lp = reinterpret_cast<__nv_bfloat162*>(g_in_lo + 4 * (size_t)i);
        hp[0] = __nv_bfloat162(h0, h1); hp[1] = __nv_bfloat162(h2, h3);
        lp[0] = __nv_bfloat162(l0, l1); lp[1] = __nv_bfloat162(l2, l3);
        return;
    }
    const float* in;
    bf16 *hi, *lo;
    int Cc, Rout, tidx;
    float scale = 1.0f;
    if (b < 2304)      { in = Wv;  hi = g_wvT_hi;  lo = g_wvT_lo;  Cc = CDIM; Rout = CDIM; tidx = b; }
    else if (b < 3072) { in = Wq;  hi = g_wqkT_hi; lo = g_wqkT_lo; Cc = 512;  Rout = CDIM; tidx = b - 2304; scale = 0.125f; }
    else if (b < 3840) { in = Wk;  hi = g_wqkT_hi + 512 * CDIM; lo = g_wqkT_lo + 512 * CDIM;
                         Cc = 512;  Rout = CDIM; tidx = b - 3072; }
    else if (b < 6144) { in = We;  hi = g_weT_hi;  lo = g_weT_lo;  Cc = CDIM; Rout = CDIM; tidx = b - 3840; }
    else               { in = Wrk; hi = g_wrkT_hi; lo = g_wrkT_lo; Cc = 512;  Rout = 192;  tidx = b - 6144; }
    int ntc = Cc / 32;
    int c0 = (tidx % ntc) * 32, r0 = (tidx / ntc) * 32;
    int tx = tid & 31, ty = tid >> 5;
    #pragma unroll
    for (int i = 0; i < 32; i += 8)
        t[ty + i][tx] = in[(size_t)(r0 + ty + i) * Cc + c0 + tx];
    __syncthreads();
    #pragma unroll
    for (int i = 0; i < 32; i += 8) {
        size_t o = (size_t)(c0 + ty + i) * Rout + r0 + tx;
        split2(t[tx][ty + i] * scale, hi + o, lo + o);
    }
}

// vT split (needs g_v)
__global__ void tsplit_kernel(const float* __restrict__ in, bf16* __restrict__ hi,
                              bf16* __restrict__ lo, int R, int Cc, size_t sIn, size_t sOut) {
    __shared__ float t[32][33];
    int z = blockIdx.z;
    in += (size_t)z * sIn;
    int c0 = blockIdx.x * 32, r0 = blockIdx.y * 32;
    int tx = threadIdx.x, ty = threadIdx.y;
    #pragma unroll
    for (int i = 0; i < 32; i += 8)
        t[ty + i][tx] = in[(size_t)(r0 + ty + i) * Cc + c0 + tx];
    __syncthreads();
    #pragma unroll
    for (int i = 0; i < 32; i += 8) {
        size_t o = (size_t)z * sOut + (size_t)(c0 + ty + i) * R + r0 + tx;
        split2(t[tx][ty + i], hi + o, lo + o);
    }
}

// fused: q+bias splits, k split, rk split
#define QKSZ (HH * TT * KD)
#define RKSZ (HH * RDP * KD)
__global__ void fuse_split_kernel(const float* __restrict__ rwb, const float* __restrict__ rrb) {
    int idx = blockIdx.x * blockDim.x + threadIdx.x;
    if (idx < QKSZ) {
        int h = idx / (TT * KD);
        int d = idx & (KD - 1);
        float qv = g_qk[idx];     // already scaled by 1/8 (baked into Wq)
        split2(qv + rwb[h * KD + d], &g_qw_hi[idx], &g_qw_lo[idx]);
        split2(qv + rrb[h * KD + d], &g_qr_hi[idx], &g_qr_lo[idx]);
    } else if (idx < 2 * QKSZ) {
        int i = idx - QKSZ;
        split2(g_qk[QKSZ + i], &g_k_hi[i], &g_k_lo[i]);
    } else if (idx < 2 * QKSZ + RKSZ) {
        int i = idx - 2 * QKSZ;
        split2(g_rkf[i], &g_rk_hi[i], &g_rk_lo[i]);
    }
}

// ========================= fused V + QK projection GEMM (NT=64) =========================
__global__ void __launch_bounds__(256)
proj_gemm() {
    constexpr int AT = 128 * 64;
    constexpr int BT = 64 * 64;
    constexpr int SS = 2 * AT + 2 * BT;
    constexpr int NG = 2;
    extern __shared__ char smem[];
    const uint32_t sbase = smem_to_u32(smem);
    int tid = threadIdx.x, wid = tid >> 5, lane = tid & 31;
    int b = blockIdx.x;

    const bf16 *Bhi, *Blo;
    float* C;
    int hd, m0, n0;
    if (b < 288) {                    // V projection
        n0 = (b % 24) * 64;  m0 = (b / 24) * 128;
        Bhi = g_wvT_hi;  Blo = g_wvT_lo;  C = g_v;  hd = VD;
    } else {                          // QK projection
        int t = b - 288;
        n0 = (t % 16) * 64;  m0 = (t / 16) * 128;
        Bhi = g_wqkT_hi;  Blo = g_wqkT_lo;  C = g_qk;  hd = KD;
    }
    const bf16* Ahi = g_in_hi;
    const bf16* Alo = g_in_lo;
    constexpr int Kt = CDIM, M = TT;
    int mw = (wid & 3) * 32, nw = (wid >> 2) * 32;

    float acc[2][NG * 2][4];
    #pragma unroll
    for (int a = 0; a < 2; a++)
        #pragma unroll
        for (int b2 = 0; b2 < NG * 2; b2++)
            #pragma unroll
            for (int c = 0; c < 4; c++) acc[a][b2][c] = 0.f;

    constexpr int nblk = Kt >> 5;

    auto issue_stage = [&](int blk, int slot) {
        int k0 = blk * 32;
        uint32_t so = sbase + slot * SS;
        #pragma unroll
        for (int i = tid; i < 128 * 4; i += 256) {
            int r = i >> 2, c = i & 3;
            uint32_t d = so + (((uint32_t)r << 2) + (uint32_t)(c ^ (r & 3))) * 16;
            CP_ASYNC16(d,      Ahi + (size_t)(m0 + r) * Kt + k0 + c * 8);
            CP_ASYNC16(d + AT, Alo + (size_t)(m0 + r) * Kt + k0 + c * 8);
        }
        #pragma unroll
        for (int i = tid; i < 64 * 4; i += 256) {
            int r = i >> 2, c = i & 3;
            uint32_t d = so + 2 * AT + (((uint32_t)r << 2) + (uint32_t)(c ^ (r & 3))) * 16;
            CP_ASYNC16(d,      Bhi + (size_t)(n0 + r) * Kt + k0 + c * 8);
            CP_ASYNC16(d + BT, Blo + (size_t)(n0 + r) * Kt + k0 + c * 8);
        }
    };

    issue_stage(0, 0);
    CP_COMMIT();
    issue_stage(1, 1);
    CP_COMMIT();
    int slot = 0, nslot = 2;
    for (int blk = 0; blk < nblk; blk++) {
        if (blk + 2 < nblk) issue_stage(blk + 2, nslot);
        CP_COMMIT();
        CP_WAIT2();
        __syncthreads();
        uint32_t so = sbase + slot * SS;
        #pragma unroll
        for (int ks = 0; ks < 2; ks++) {
            uint32_t ah[8], al[8];
            #pragma unroll
            for (int fm = 0; fm < 2; fm++) {
                int ra = mw + fm * 16 + (lane & 15);
                int ca = ks * 2 + (lane >> 4);
                uint32_t off = (((uint32_t)ra << 2) + (uint32_t)(ca ^ (ra & 3))) * 16;
                ldm_x4(ah + fm * 4, so + off);
                ldm_x4(al + fm * 4, so + AT + off);
            }
            #pragma unroll
            for (int nt = 0; nt < NG; nt++) {
                int rb = nw + nt * 16 + ((lane >> 4) & 1) * 8 + (lane & 7);
                int cb = ks * 2 + ((lane >> 3) & 1);
                uint32_t offb = (((uint32_t)rb << 2) + (uint32_t)(cb ^ (rb & 3))) * 16;
                uint32_t bh[4], bl[4];
                ldm_x4(bh, so + 2 * AT + offb);
                ldm_x4(bl, so + 2 * AT + BT + offb);
                #pragma unroll
                for (int fm = 0; fm < 2; fm++) {
                    #pragma unroll
                    for (int hf = 0; hf < 2; hf++) {
                        float* cc = acc[fm][nt * 2 + hf];
                        mma_bf16(cc, ah + fm * 4, bh + hf * 2);
                        mma_bf16(cc, ah + fm * 4, bl + hf * 2);
                        mma_bf16(cc, al + fm * 4, bh + hf * 2);
                    }
                }
            }
        }
        __syncthreads();
        slot = (slot == 2) ? 0 : slot + 1;
        nslot = (nslot == 2) ? 0 : nslot + 1;
    }

    int g = lane >> 2, tg = lane & 3;
    #pragma unroll
    for (int fm = 0; fm < 2; fm++) {
        #pragma unroll
        for (int fn = 0; fn < NG * 2; fn++) {
            int n = n0 + nw + fn * 8 + tg * 2;
            int m = m0 + mw + fm * 16 + g;
            float* cc = acc[fm][fn];
            #pragma unroll
            for (int hrow = 0; hrow < 2; hrow++) {
                int mm = m + hrow * 8;
                #pragma unroll
                for (int jj = 0; jj < 2; jj++) {
                    int nn = n + jj;
                    size_t o = ((size_t)(nn / hd) * M + mm) * (size_t)hd + (nn % hd);
                    C[o] = cc[hrow * 2 + jj];
                }
            }
        }
    }
}

// ========================= combined logits GEMM (content + banded rel, NT=128) =========================
// grid (25, 12, 8): x<12 -> content tile; x>=12 -> rel band tile
__global__ void __launch_bounds__(256)
logits_gemm() {
    constexpr int AT = 128 * 64;
    constexpr int BT = 128 * 64;
    constexpr int SS = 2 * AT + 2 * BT;
    constexpr int NG = 4;
    extern __shared__ char smem[];
    const uint32_t sbase = smem_to_u32(smem);
    int tid = threadIdx.x, wid = tid >> 5, lane = tid & 31;
    int z = blockIdx.z, y = blockIdx.y, x = blockIdx.x;
    int m0 = y * 128;
    const bf16 *Ahi, *Alo, *Bhi, *Blo;
    float* C;
    int ldc, n0;
    if (x < 12) {
        Ahi = g_qw_hi + (size_t)z * TT * KD;  Alo = g_qw_lo + (size_t)z * TT * KD;
        Bhi = g_k_hi  + (size_t)z * TT * KD;  Blo = g_k_lo  + (size_t)z * TT * KD;
        C = g_content + (size_t)z * TT * TT;  ldc = TT;  n0 = x * 128;
    } else {
        Ahi = g_qr_hi + (size_t)z * TT * KD;  Alo = g_qr_lo + (size_t)z * TT * KD;
        Bhi = g_rk_hi + (size_t)z * RDP * KD; Blo = g_rk_lo + (size_t)z * RDP * KD;
        C = g_rel + (size_t)z * TT * RDP;     ldc = RDP; n0 = (11 - y + (x - 12)) * 128;
    }
    constexpr int Kt = KD;
    int mw = (wid & 3) * 32, nw = (wid >> 2) * 64;

    float acc[2][NG * 2][4];
    #pragma unroll
    for (int a = 0; a < 2; a++)
        #pragma unroll
        for (int b2 = 0; b2 < NG * 2; b2++)
            #pragma unroll
            for (int c = 0; c < 4; c++) acc[a][b2][c] = 0.f;

    auto issue_stage = [&](int blk, int slot) {
        int k0 = blk * 32;
        uint32_t so = sbase + slot * SS;
        #pragma unroll
        for (int i = tid; i < 128 * 4; i += 256) {
            int r = i >> 2, c = i & 3;
            uint32_t d = so + (((uint32_t)r << 2) + (uint32_t)(c ^ (r & 3))) * 16;
            CP_ASYNC16(d,      Ahi + (size_t)(m0 + r) * Kt + k0 + c * 8);
            CP_ASYNC16(d + AT, Alo + (size_t)(m0 + r) * Kt + k0 + c * 8);
        }
        #pragma unroll
        for (int i = tid; i < 128 * 4; i += 256) {
            int r = i >> 2, c = i & 3;
            uint32_t d = so + 2 * AT + (((uint32_t)r << 2) + (uint32_t)(c ^ (r & 3))) * 16;
            CP_ASYNC16(d,      Bhi + (size_t)(n0 + r) * Kt + k0 + c * 8);
            CP_ASYNC16(d + BT, Blo + (size_t)(n0 + r) * Kt + k0 + c * 8);
        }
    };

    issue_stage(0, 0);
    CP_COMMIT();
    issue_stage(1, 1);
    CP_COMMIT();
    #pragma unroll
    for (int blk = 0; blk < 2; blk++) {
        CP_COMMIT();
        CP_WAIT2();
        __syncthreads();
        uint32_t so = sbase + blk * SS;
        #pragma unroll
        for (int ks = 0; ks < 2; ks++) {
            uint32_t ah[8], al[8];
            #pragma unroll
            for (int fm = 0; fm < 2; fm++) {
                int ra = mw + fm * 16 + (lane & 15);
                int ca = ks * 2 + (lane >> 4);
                uint32_t off = (((uint32_t)ra << 2) + (uint32_t)(ca ^ (ra & 3))) * 16;
                ldm_x4(ah + fm * 4, so + off);
                ldm_x4(al + fm * 4, so + AT + off);
            }
            #pragma unroll
            for (int nt = 0; nt < NG; nt++) {
                int rb = nw + nt * 16 + ((lane >> 4) & 1) * 8 + (lane & 7);
                int cb = ks * 2 + ((lane >> 3) & 1);
                uint32_t offb = (((uint32_t)rb << 2) + (uint32_t)(cb ^ (rb & 3))) * 16;
                uint32_t bh[4], bl[4];
                ldm_x4(bh, so + 2 * AT + offb);
                ldm_x4(bl, so + 2 * AT + BT + offb);
                #pragma unroll
                for (int fm = 0; fm < 2; fm++) {
                    #pragma unroll
                    for (int hf = 0; hf < 2; hf++) {
                        float* cc = acc[fm][nt * 2 + hf];
                        mma_bf16(cc, ah + fm * 4, bh + hf * 2);
                        mma_bf16(cc, ah + fm * 4, bl + hf * 2);
                        mma_bf16(cc, al + fm * 4, bh + hf * 2);
                    }
                }
            }
        }
        __syncthreads();
    }

    int g = lane >> 2, tg = lane & 3;
    #pragma unroll
    for (int fm = 0; fm < 2; fm++) {
        #pragma unroll
        for (int fn = 0; fn < NG * 2; fn++) {
            int n = n0 + nw + fn * 8 + tg * 2;
            int m = m0 + mw + fm * 16 + g;
            float* cc = acc[fm][fn];
            #pragma unroll
            for (int hrow = 0; hrow < 2; hrow++) {
                int mm = m + hrow * 8;
                #pragma unroll
                for (int jj = 0; jj < 2; jj++)
                    C[(size_t)mm * ldc + n + jj] = cc[hrow * 2 + jj];
            }
        }
    }
}

// ========================= generic HMMA GEMM (3-stage) =========================
template <int NT, bool BF16OUT>
__global__ void __launch_bounds__(256)
mma_gemm(const bf16* __restrict__ Ahi, const bf16* __restrict__ Alo, size_t sA,
         const bf16* __restrict__ Bhi, const bf16* __restrict__ Blo, size_t sB,
         float* __restrict__ C, bf16* __restrict__ Chi, bf16* __restrict__ Clo,
         int ldc, size_t sC,
         int M, int Kt, float alpha, const float* __restrict__ bias, int hd) {
    constexpr int AT = 128 * 64;
    constexpr int BT = NT * 64;
    constexpr int SS = 2 * AT + 2 * BT;
    constexpr int WN = NT / 2;
    constexpr int NG = WN / 16;
    extern __shared__ char smem[];
    const uint32_t sbase = smem_to_u32(smem);
    int tid = threadIdx.x, wid = tid >> 5, lane = tid & 31;
    int z = blockIdx.z;
    int m0 = blockIdx.y * 128;
    int n0 = blockIdx.x * NT;
    Ahi += (size_t)z * sA;  Alo += (size_t)z * sA;
    Bhi += (size_t)z * sB;  Blo += (size_t)z * sB;
    int mw = (wid & 3) * 32, nw = (wid >> 2) * WN;

    float acc[2][NG * 2][4];
    #pragma unroll
    for (int a = 0; a < 2; a++)
        #pragma unroll
        for (int b = 0; b < NG * 2; b++)
            #pragma unroll
            for (int c = 0; c < 4; c++) acc[a][b][c] = 0.f;

    int nblk = Kt >> 5;

    auto issue_stage = [&](int blk, int slot) {
        int k0 = blk * 32;
        uint32_t so = sbase + slot * SS;
        #pragma unroll
        for (int i = tid; i < 128 * 4; i += 256) {
            int r = i >> 2, c = i & 3;
            uint32_t d = so + (((uint32_t)r << 2) + (uint32_t)(c ^ (r & 3))) * 16;
            CP_ASYNC16(d,      Ahi + (size_t)(m0 + r) * Kt + k0 + c * 8);
            CP_ASYNC16(d + AT, Alo + (size_t)(m0 + r) * Kt + k0 + c * 8);
        }
        #pragma unroll
        for (int i = tid; i < NT * 4; i += 256) {
            int r = i >> 2, c = i & 3;
            uint32_t d = so + 2 * AT + (((uint32_t)r << 2) + (uint32_t)(c ^ (r & 3))) * 16;
            CP_ASYNC16(d,      Bhi + (size_t)(n0 + r) * Kt + k0 + c * 8);
            CP_ASYNC16(d + BT, Blo + (size_t)(n0 + r) * Kt + k0 + c * 8);
        }
    };

    issue_stage(0, 0);
    CP_COMMIT();
    issue_stage(1, 1);
    CP_COMMIT();
    int slot = 0, nslot = 2;
    for (int blk = 0; blk < nblk; blk++) {
        if (blk + 2 < nblk) issue_stage(blk + 2, nslot);
        CP_COMMIT();
        CP_WAIT2();
        __syncthreads();
        uint32_t so = sbase + slot * SS;
        #pragma unroll
        for (int ks = 0; ks < 2; ks++) {
            uint32_t ah[8], al[8];
            #pragma unroll
            for (int fm = 0; fm < 2; fm++) {
                int ra = mw + fm * 16 + (lane & 15);
                int ca = ks * 2 + (lane >> 4);
                uint32_t off = (((uint32_t)ra << 2) + (uint32_t)(ca ^ (ra & 3))) * 16;
                ldm_x4(ah + fm * 4, so + off);
                ldm_x4(al + fm * 4, so + AT + off);
            }
            #pragma unroll
            for (int nt = 0; nt < NG; nt++) {
                int rb = nw + nt * 16 + ((lane >> 4) & 1) * 8 + (lane & 7);
                int cb = ks * 2 + ((lane >> 3) & 1);
                uint32_t offb = (((uint32_t)rb << 2) + (uint32_t)(cb ^ (rb & 3))) * 16;
                uint32_t bh[4], bl[4];
                ldm_x4(bh, so + 2 * AT + offb);
                ldm_x4(bl, so + 2 * AT + BT + offb);
                #pragma unroll
                for (int fm = 0; fm < 2; fm++) {
                    #pragma unroll
                    for (int hf = 0; hf < 2; hf++) {
                        float* cc = acc[fm][nt * 2 + hf];
                        mma_bf16(cc, ah + fm * 4, bh + hf * 2);
                        mma_bf16(cc, ah + fm * 4, bl + hf * 2);
                        mma_bf16(cc, al + fm * 4, bh + hf * 2);
                    }
                }
            }
        }
        __syncthreads();
        slot = (slot == 2) ? 0 : slot + 1;
        nslot = (nslot == 2) ? 0 : nslot + 1;
    }

    int g = lane >> 2, tg = lane & 3;
    #pragma unroll
    for (int fm = 0; fm < 2; fm++) {
        #pragma unroll
        for (int fn = 0; fn < NG * 2; fn++) {
            int n = n0 + nw + fn * 8 + tg * 2;
            int m = m0 + mw + fm * 16 + g;
            float* cc = acc[fm][fn];
            #pragma unroll
            for (int hrow = 0; hrow < 2; hrow++) {
                int mm = m + hrow * 8;
                if (BF16OUT) {
                    size_t o = hd ? ((size_t)(n / hd) * M + mm) * (size_t)hd + (n % hd)
                                  : (size_t)z * sC + (size_t)mm * ldc + n;
                    bf16 h0, l0, h1, l1;
                    split2(alpha * cc[hrow * 2 + 0], &h0, &l0);
                    split2(alpha * cc[hrow * 2 + 1], &h1, &l1);
                    *(__nv_bfloat162*)(Chi + o) = __nv_bfloat162(h0, h1);
                    *(__nv_bfloat162*)(Clo + o) = __nv_bfloat162(l0, l1);
                } else {
                    #pragma unroll
                    for (int jj = 0; jj < 2; jj++) {
                        int nn = n + jj;
                        float v = alpha * cc[hrow * 2 + jj];
                        if (bias) v += bias[nn];
                        size_t o;
                        if (hd) o = ((size_t)(nn / hd) * M + mm) * (size_t)hd + (nn % hd);
                        else    o = (size_t)z * sC + (size_t)mm * ldc + nn;
                        C[o] = v;
                    }
                }
            }
        }
    }
}

// ========================= combine + softmax + split-P =========================
__global__ void softmax_kernel() {
    __shared__ float s[256];
    int row = blockIdx.x;
    int q = row % TT;
    const float* cont = g_content + (size_t)row * TT;
    const float* rel  = g_rel + (size_t)row * RDP + (TT - 1 - q);
    bf16* phi = g_p_hi + (size_t)row * TT;
    bf16* plo = g_p_lo + (size_t)row * TT;
    int t = threadIdx.x;
    float v[6];
    float mx = -1e30f;
    #pragma unroll
    for (int i = 0; i < 6; i++) {
        int j = t + i * 256;
        v[i] = cont[j] + rel[j];
        mx = fmaxf(mx, v[i]);
    }
    s[t] = mx; __syncthreads();
    for (int o = 128; o > 0; o >>= 1) { if (t < o) s[t] = fmaxf(s[t], s[t + o]); __syncthreads(); }
    mx = s[0]; __syncthreads();
    float sum = 0.f;
    #pragma unroll
    for (int i = 0; i < 6; i++) { v[i] = expf(v[i] - mx); sum += v[i]; }
    s[t] = sum; __syncthreads();
    for (int o = 128; o > 0; o >>= 1) { if (t < o) s[t] += s[t + o]; __syncthreads(); }
    float inv = 1.0f / s[0];
    #pragma unroll
    for (int i = 0; i < 6; i++) {
        int j = t + i * 256;
        split2(v[i] * inv, phi + j, plo + j);
    }
}

// ========================= launch =========================
static void* dev_ptr(const void* symbol) {
    void* p = nullptr;
    cudaGetSymbolAddress(&p, symbol);
    return p;
}

extern "C" void kernel_launch(void* const* d_in, const int* in_sizes, int n_in,
                              void* d_out, int out_size) {
    const float* inputs = (const float*)d_in[0];
    const float* Wq  = (const float*)d_in[1];
    const float* Wk  = (const float*)d_in[2];
    const float* Wv  = (const float*)d_in[3];
    const float* Wrk = (const float*)d_in[4];
    const float* rwb = (const float*)d_in[5];
    const float* rrb = (const float*)d_in[6];
    const float* We  = (const float*)d_in[7];
    const float* be  = (const float*)d_in[8];
    float* out = (float*)d_out;

    const int SM128 = 3 * (2 * 128 * 64 + 2 * 128 * 64);  // 98304
    const int SM64  = 3 * (2 * 128 * 64 + 2 * 64 * 64);   // 73728
    cudaFuncSetAttribute((const void*)mma_gemm<64, false>,  cudaFuncAttributeMaxDynamicSharedMemorySize, SM64);
    cudaFuncSetAttribute((const void*)mma_gemm<64, true>,   cudaFuncAttributeMaxDynamicSharedMemorySize, SM64);
    cudaFuncSetAttribute((const void*)proj_gemm,            cudaFuncAttributeMaxDynamicSharedMemorySize, SM64);
    cudaFuncSetAttribute((const void*)logits_gemm,          cudaFuncAttributeMaxDynamicSharedMemorySize, SM128);

    float* pv = (float*)dev_ptr(g_v);
    float* prkf = (float*)dev_ptr(g_rkf);
    bf16* pe_hi = (bf16*)dev_ptr(g_pe_hi);   bf16* pe_lo = (bf16*)dev_ptr(g_pe_lo);
    bf16* wrkT_hi = (bf16*)dev_ptr(g_wrkT_hi); bf16* wrkT_lo = (bf16*)dev_ptr(g_wrkT_lo);
    bf16* weT_hi = (bf16*)dev_ptr(g_weT_hi); bf16* weT_lo = (bf16*)dev_ptr(g_weT_lo);
    bf16* vT_hi = (bf16*)dev_ptr(g_vT_hi); bf16* vT_lo = (bf16*)dev_ptr(g_vT_lo);
    bf16* p_hi = (bf16*)dev_ptr(g_p_hi); bf16* p_lo = (bf16*)dev_ptr(g_p_lo);
    bf16* at_hi = (bf16*)dev_ptr(g_at_hi); bf16* at_lo = (bf16*)dev_ptr(g_at_lo);

    dim3 tb(32, 8);

    // 1: gamma features
    pf_gamma_raw_kernel<<<(RD * NB + 255) / 256, 256>>>();
    // 2: fused prep (input split + all weight transpose-splits)
    prep_kernel<<<8544, 256>>>(inputs, Wq, Wk, Wv, We, Wrk);
    // 3: gamma max
    pf_max_kernel<<<1, 1024>>>();
    // 4: fused V + QK projections (480 CTAs) — ncu-profiled slot
    proj_gemm<<<480, 256, SM64>>>();
    // 5: positional feature build (needs gmax)
    pf_build_kernel<<<(RDP * 96 + 255) / 256, 256>>>();
    // 6: RK projection (K=192) -> head-major fp32
    mma_gemm<64, false><<<dim3(8, 24, 1), 256, SM64>>>(pe_hi, pe_lo, 0, wrkT_hi, wrkT_lo, 0,
        prkf, nullptr, nullptr, 0, 0, RDP, 192, 1.0f, nullptr, KD);
    // 7: fused glue: qw/qr (raw biases), k split, rk split
    fuse_split_kernel<<<(2 * QKSZ + RKSZ + 255) / 256, 256>>>(rwb, rrb);
    // 8: vT split
    tsplit_kernel<<<dim3(VD / 32, TT / 32, HH), tb>>>(pv, vT_hi, vT_lo, TT, VD,
        (size_t)TT * VD, (size_t)VD * TT);
    // 9: combined content + rel logits (K=64, 2400 CTAs)
    logits_gemm<<<dim3(25, 12, HH), 256, SM128>>>();
    // 10: combine + softmax -> P (bf16 hi/lo)
    softmax_kernel<<<HH * TT, 256>>>();
    // 11: P @ V (K=1536) -> attn split bf16 directly
    mma_gemm<64, true><<<dim3(3, 12, HH), 256, SM64>>>(p_hi, p_lo, (size_t)TT * TT,
        vT_hi, vT_lo, (size_t)VD * TT, nullptr, at_hi, at_lo, CDIM, (size_t)VD,
        TT, TT, 1.0f, nullptr, 0);
    // 12: out = attn @ We + be (K=1536, NT=64)
    mma_gemm<64, false><<<dim3(24, 12, 1), 256, SM64>>>(at_hi, at_lo, 0, weT_hi, weT_lo, 0,
        out, nullptr, nullptr, CDIM, 0, TT, CDIM, 1.0f, be, 0);
}

// round 15
// speedup vs baseline: 1.0364x; 1.0364x over previous
#include <cuda_runtime.h>
#include <cuda_bf16.h>
#include <math.h>
#include <stdint.h>

#define TT   1536
#define CDIM 1536
#define HH   8
#define KD   64
#define VD   192
#define RD   3071
#define RDP  3072
#define NB   32

typedef __nv_bfloat16 bf16;

// ========================= helpers =========================
__device__ __forceinline__ uint32_t smem_to_u32(const void* p) {
    uint32_t a;
    asm("{ .reg .u64 t; cvta.to.shared.u64 t, %1; cvt.u32.u64 %0, t; }" : "=r"(a) : "l"(p));
    return a;
}
#define CP_ASYNC16(dst, src) \
    asm volatile("cp.async.cg.shared.global [%0], [%1], 16;" :: "r"(dst), "l"(src))
#define CP_COMMIT() asm volatile("cp.async.commit_group;" ::: "memory")
#define CP_WAIT2()  asm volatile("cp.async.wait_group 2;" ::: "memory")

__device__ __forceinline__ void ldm_x4(uint32_t* r, uint32_t addr) {
    asm volatile("ldmatrix.sync.aligned.m8n8.x4.shared.b16 {%0,%1,%2,%3}, [%4];"
        : "=r"(r[0]), "=r"(r[1]), "=r"(r[2]), "=r"(r[3]) : "r"(addr));
}
__device__ __forceinline__ void mma_bf16(float* c, const uint32_t* a, const uint32_t* b) {
    asm volatile("mma.sync.aligned.m16n8k16.row.col.f32.bf16.bf16.f32 "
        "{%0,%1,%2,%3}, {%4,%5,%6,%7}, {%8,%9}, {%0,%1,%2,%3};"
        : "+f"(c[0]), "+f"(c[1]), "+f"(c[2]), "+f"(c[3])
        : "r"(a[0]), "r"(a[1]), "r"(a[2]), "r"(a[3]), "r"(b[0]), "r"(b[1]));
}

// ========================= scratch =========================
__device__ float g_gprobs[RD * NB];
__device__ float g_gmax;
__device__ __align__(16) bf16 g_pe_hi[RDP * 192], g_pe_lo[RDP * 192];
__device__ __align__(16) bf16 g_wqkT_hi[1024 * CDIM], g_wqkT_lo[1024 * CDIM];
__device__ __align__(16) bf16 g_wvT_hi[CDIM * CDIM], g_wvT_lo[CDIM * CDIM];
__device__ __align__(16) bf16 g_weT_hi[CDIM * CDIM], g_weT_lo[CDIM * CDIM];
__device__ __align__(16) bf16 g_wrkT_hi[512 * 192], g_wrkT_lo[512 * 192];
__device__ __align__(16) bf16 g_in_hi[TT * CDIM], g_in_lo[TT * CDIM];
__device__ __align__(16) float g_qk[2 * HH * TT * KD];   // heads 0-7: q (pre-scaled), 8-15: k
__device__ __align__(16) float g_v[HH * TT * VD];
__device__ __align__(16) float g_rkf[HH * RDP * KD];
__device__ __align__(16) bf16 g_qw_hi[HH * TT * KD], g_qw_lo[HH * TT * KD];
__device__ __align__(16) bf16 g_qr_hi[HH * TT * KD], g_qr_lo[HH * TT * KD];
__device__ __align__(16) bf16 g_k_hi[HH * TT * KD], g_k_lo[HH * TT * KD];
__device__ __align__(16) bf16 g_rk_hi[HH * RDP * KD], g_rk_lo[HH * RDP * KD];
__device__ __align__(16) bf16 g_vT_hi[HH * VD * TT], g_vT_lo[HH * VD * TT];
__device__ __align__(16) float g_content[(size_t)HH * TT * TT];
__device__ __align__(16) float g_rel[(size_t)HH * TT * RDP];
__device__ __align__(16) bf16 g_p_hi[(size_t)HH * TT * TT], g_p_lo[(size_t)HH * TT * TT];
__device__ __align__(16) bf16 g_at_hi[TT * CDIM], g_at_lo[TT * CDIM];

__device__ __forceinline__ void split2(float x, bf16* hi, bf16* lo) {
    bf16 h = __float2bfloat16(x);
    *hi = h;
    *lo = __float2bfloat16(x - __bfloat162float(h));
}

// ========================= positional features =========================
__global__ void pf_gamma_raw_kernel() {
    int idx = blockIdx.x * blockDim.x + threadIdx.x;
    if (idx >= RD * NB) return;
    int r = idx / NB, i = idx % NB;
    double x    = fabs((double)(r - (TT - 1)));
    double mean = 48.0 * (i + 1);
    double conc = (mean / 24.0) * (mean / 24.0);
    double rate = mean / 576.0;
    double lu   = (conc - 1.0) * log(x) - rate * x;
    double ln   = lgamma(conc) - conc * log(rate);
    g_gprobs[idx] = (float)exp(lu - ln) + 1e-8f;
}

__global__ void pf_max_kernel() {
    __shared__ float s[1024];
    int t = threadIdx.x;
    float m = 0.f;
    for (int i = t; i < RD * NB; i += 1024) m = fmaxf(m, g_gprobs[i]);
    s[t] = m; __syncthreads();
    for (int o = 512; o > 0; o >>= 1) { if (t < o) s[t] = fmaxf(s[t], s[t + o]); __syncthreads(); }
    if (t == 0) g_gmax = s[0];
}

__global__ void pf_build_kernel() {
    int idx = blockIdx.x * blockDim.x + threadIdx.x;
    if (idx >= RDP * 96) return;
    int r = idx / 96, i = idx % 96;
    float v1 = 0.f, v2 = 0.f;
    if (r < RD) {
        float p  = (float)(r - (TT - 1));
        float ap = fabsf(p);
        float val;
        if (i < 32) {
            double mr = log(1536.0) / log(2.0);
            double hl = pow(2.0, 3.0 + (double)i * (mr - 3.0) / 31.0);
            val = expf(-(float)(0.6931471805599453 / hl) * ap);
        } else if (i < 64) {
            float cw = exp2f((float)(i - 32 + 1)) - 1.0f;
            val = (cw > ap) ? 1.0f : 0.0f;
        } else {
            val = g_gprobs[r * NB + (i - 64)] / g_gmax;
        }
        float sg = (p > 0.f) ? 1.f : ((p < 0.f) ? -1.f : 0.f);
        v1 = val; v2 = sg * val;
    }
    split2(v1, &g_pe_hi[r * 192 + i],      &g_pe_lo[r * 192 + i]);
    split2(v2, &g_pe_hi[r * 192 + 96 + i], &g_pe_lo[r * 192 + 96 + i]);
}

// ========================= fused prep: input split + all weight transpose-splits =========================
__global__ void prep_kernel(const float* __restrict__ inputs,
                            const float* __restrict__ Wq, const float* __restrict__ Wk,
                            const float* __restrict__ Wv, const float* __restrict__ We,
                            const float* __restrict__ Wrk) {
    __shared__ float t[32][33];
    int b = blockIdx.x;
    int tid = threadIdx.x;
    if (b >= 6240) {
        int i = (b - 6240) * 256 + tid;
        float4 v = reinterpret_cast<const float4*>(inputs)[i];
        bf16 h0, l0, h1, l1, h2, l2, h3, l3;
        split2(v.x, &h0, &l0); split2(v.y, &h1, &l1);
        split2(v.z, &h2, &l2); split2(v.w, &h3, &l3);
        __nv_bfloat162* hp = reinterpret_cast<__nv_bfloat162*>(g_in_hi + 4 * (size_t)i);
        __nv_bfloat162* lp = reinterpret_cast<__nv_bfloat162*>(g_in_lo + 4 * (size_t)i);
        hp[0] = __nv_bfloat162(h0, h1); hp[1] = __nv_bfloat162(h2, h3);
        lp[0] = __nv_bfloat162(l0, l1); lp[1] = __nv_bfloat162(l2, l3);
        return;
    }
    const float* in;
    bf16 *hi, *lo;
    int Cc, Rout, tidx;
    float scale = 1.0f;
    if (b < 2304)      { in = Wv;  hi = g_wvT_hi;  lo = g_wvT_lo;  Cc = CDIM; Rout = CDIM; tidx = b; }
    else if (b < 3072) { in = Wq;  hi = g_wqkT_hi; lo = g_wqkT_lo; Cc = 512;  Rout = CDIM; tidx = b - 2304; scale = 0.125f; }
    else if (b < 3840) { in = Wk;  hi = g_wqkT_hi + 512 * CDIM; lo = g_wqkT_lo + 512 * CDIM;
                         Cc = 512;  Rout = CDIM; tidx = b - 3072; }
    else if (b < 6144) { in = We;  hi = g_weT_hi;  lo = g_weT_lo;  Cc = CDIM; Rout = CDIM; tidx = b - 3840; }
    else               { in = Wrk; hi = g_wrkT_hi; lo = g_wrkT_lo; Cc = 512;  Rout = 192;  tidx = b - 6144; }
    int ntc = Cc / 32;
    int c0 = (tidx % ntc) * 32, r0 = (tidx / ntc) * 32;
    int tx = tid & 31, ty = tid >> 5;
    #pragma unroll
    for (int i = 0; i < 32; i += 8)
        t[ty + i][tx] = in[(size_t)(r0 + ty + i) * Cc + c0 + tx];
    __syncthreads();
    #pragma unroll
    for (int i = 0; i < 32; i += 8) {
        size_t o = (size_t)(c0 + ty + i) * Rout + r0 + tx;
        split2(t[tx][ty + i] * scale, hi + o, lo + o);
    }
}

// vT split
__global__ void tsplit_kernel(const float* __restrict__ in, bf16* __restrict__ hi,
                              bf16* __restrict__ lo, int R, int Cc, size_t sIn, size_t sOut) {
    __shared__ float t[32][33];
    int z = blockIdx.z;
    in += (size_t)z * sIn;
    int c0 = blockIdx.x * 32, r0 = blockIdx.y * 32;
    int tx = threadIdx.x, ty = threadIdx.y;
    #pragma unroll
    for (int i = 0; i < 32; i += 8)
        t[ty + i][tx] = in[(size_t)(r0 + ty + i) * Cc + c0 + tx];
    __syncthreads();
    #pragma unroll
    for (int i = 0; i < 32; i += 8) {
        size_t o = (size_t)z * sOut + (size_t)(c0 + ty + i) * R + r0 + tx;
        split2(t[tx][ty + i], hi + o, lo + o);
    }
}

// fused: q+bias splits, k split, rk split
#define QKSZ (HH * TT * KD)
#define RKSZ (HH * RDP * KD)
__global__ void fuse_split_kernel(const float* __restrict__ rwb, const float* __restrict__ rrb) {
    int idx = blockIdx.x * blockDim.x + threadIdx.x;
    if (idx < QKSZ) {
        int h = idx / (TT * KD);
        int d = idx & (KD - 1);
        float qv = g_qk[idx];     // already scaled by 1/8 (baked into Wq)
        split2(qv + rwb[h * KD + d], &g_qw_hi[idx], &g_qw_lo[idx]);
        split2(qv + rrb[h * KD + d], &g_qr_hi[idx], &g_qr_lo[idx]);
    } else if (idx < 2 * QKSZ) {
        int i = idx - QKSZ;
        split2(g_qk[QKSZ + i], &g_k_hi[i], &g_k_lo[i]);
    } else if (idx < 2 * QKSZ + RKSZ) {
        int i = idx - 2 * QKSZ;
        split2(g_rkf[i], &g_rk_hi[i], &g_rk_lo[i]);
    }
}

// ========================= fused V + QK projection GEMM (NT=128, 240 CTAs, single wave) =========================
__global__ void __launch_bounds__(256)
proj_gemm() {
    constexpr int AT = 128 * 64;
    constexpr int BT = 128 * 64;
    constexpr int SS = 2 * AT + 2 * BT;
    constexpr int NG = 4;
    extern __shared__ char smem[];
    const uint32_t sbase = smem_to_u32(smem);
    int tid = threadIdx.x, wid = tid >> 5, lane = tid & 31;
    int b = blockIdx.x;

    const bf16 *Bhi, *Blo;
    float* C;
    int hd, m0, n0;
    if (b < 144) {                    // V projection: N=1536 -> 12 n-tiles
        n0 = (b % 12) * 128;  m0 = (b / 12) * 128;
        Bhi = g_wvT_hi;  Blo = g_wvT_lo;  C = g_v;  hd = VD;
    } else {                          // QK projection: N=1024 -> 8 n-tiles
        int t = b - 144;
        n0 = (t % 8) * 128;  m0 = (t / 8) * 128;
        Bhi = g_wqkT_hi;  Blo = g_wqkT_lo;  C = g_qk;  hd = KD;
    }
    const bf16* Ahi = g_in_hi;
    const bf16* Alo = g_in_lo;
    constexpr int Kt = CDIM, M = TT;
    int mw = (wid & 3) * 32, nw = (wid >> 2) * 64;

    float acc[2][NG * 2][4];
    #pragma unroll
    for (int a = 0; a < 2; a++)
        #pragma unroll
        for (int b2 = 0; b2 < NG * 2; b2++)
            #pragma unroll
            for (int c = 0; c < 4; c++) acc[a][b2][c] = 0.f;

    constexpr int nblk = Kt >> 5;

    auto issue_stage = [&](int blk, int slot) {
        int k0 = blk * 32;
        uint32_t so = sbase + slot * SS;
        #pragma unroll
        for (int i = tid; i < 128 * 4; i += 256) {
            int r = i >> 2, c = i & 3;
            uint32_t d = so + (((uint32_t)r << 2) + (uint32_t)(c ^ (r & 3))) * 16;
            CP_ASYNC16(d,      Ahi + (size_t)(m0 + r) * Kt + k0 + c * 8);
            CP_ASYNC16(d + AT, Alo + (size_t)(m0 + r) * Kt + k0 + c * 8);
        }
        #pragma unroll
        for (int i = tid; i < 128 * 4; i += 256) {
            int r = i >> 2, c = i & 3;
            uint32_t d = so + 2 * AT + (((uint32_t)r << 2) + (uint32_t)(c ^ (r & 3))) * 16;
            CP_ASYNC16(d,      Bhi + (size_t)(n0 + r) * Kt + k0 + c * 8);
            CP_ASYNC16(d + BT, Blo + (size_t)(n0 + r) * Kt + k0 + c * 8);
        }
    };

    issue_stage(0, 0);
    CP_COMMIT();
    issue_stage(1, 1);
    CP_COMMIT();
    int slot = 0, nslot = 2;
    for (int blk = 0; blk < nblk; blk++) {
        if (blk + 2 < nblk) issue_stage(blk + 2, nslot);
        CP_COMMIT();
        CP_WAIT2();
        __syncthreads();
        uint32_t so = sbase + slot * SS;
        #pragma unroll
        for (int ks = 0; ks < 2; ks++) {
            uint32_t ah[8], al[8];
            #pragma unroll
            for (int fm = 0; fm < 2; fm++) {
                int ra = mw + fm * 16 + (lane & 15);
                int ca = ks * 2 + (lane >> 4);
                uint32_t off = (((uint32_t)ra << 2) + (uint32_t)(ca ^ (ra & 3))) * 16;
                ldm_x4(ah + fm * 4, so + off);
                ldm_x4(al + fm * 4, so + AT + off);
            }
            #pragma unroll
            for (int nt = 0; nt < NG; nt++) {
                int rb = nw + nt * 16 + ((lane >> 4) & 1) * 8 + (lane & 7);
                int cb = ks * 2 + ((lane >> 3) & 1);
                uint32_t offb = (((uint32_t)rb << 2) + (uint32_t)(cb ^ (rb & 3))) * 16;
                uint32_t bh[4], bl[4];
                ldm_x4(bh, so + 2 * AT + offb);
                ldm_x4(bl, so + 2 * AT + BT + offb);
                #pragma unroll
                for (int fm = 0; fm < 2; fm++) {
                    #pragma unroll
                    for (int hf = 0; hf < 2; hf++) {
                        float* cc = acc[fm][nt * 2 + hf];
                        mma_bf16(cc, ah + fm * 4, bh + hf * 2);
                        mma_bf16(cc, ah + fm * 4, bl + hf * 2);
                        mma_bf16(cc, al + fm * 4, bh + hf * 2);
                    }
                }
            }
        }
        __syncthreads();
        slot = (slot == 2) ? 0 : slot + 1;
        nslot = (nslot == 2) ? 0 : nslot + 1;
    }

    int g = lane >> 2, tg = lane & 3;
    #pragma unroll
    for (int fm = 0; fm < 2; fm++) {
        #pragma unroll
        for (int fn = 0; fn < NG * 2; fn++) {
            int n = n0 + nw + fn * 8 + tg * 2;
            int m = m0 + mw + fm * 16 + g;
            float* cc = acc[fm][fn];
            #pragma unroll
            for (int hrow = 0; hrow < 2; hrow++) {
                int mm = m + hrow * 8;
                #pragma unroll
                for (int jj = 0; jj < 2; jj++) {
                    int nn = n + jj;
                    size_t o = ((size_t)(nn / hd) * M + mm) * (size_t)hd + (nn % hd);
                    C[o] = cc[hrow * 2 + jj];
                }
            }
        }
    }
}

// ========================= combined logits GEMM (content + banded rel, NT=128) =========================
__global__ void __launch_bounds__(256)
logits_gemm() {
    constexpr int AT = 128 * 64;
    constexpr int BT = 128 * 64;
    constexpr int SS = 2 * AT + 2 * BT;
    constexpr int NG = 4;
    extern __shared__ char smem[];
    const uint32_t sbase = smem_to_u32(smem);
    int tid = threadIdx.x, wid = tid >> 5, lane = tid & 31;
    int z = blockIdx.z, y = blockIdx.y, x = blockIdx.x;
    int m0 = y * 128;
    const bf16 *Ahi, *Alo, *Bhi, *Blo;
    float* C;
    int ldc, n0;
    if (x < 12) {
        Ahi = g_qw_hi + (size_t)z * TT * KD;  Alo = g_qw_lo + (size_t)z * TT * KD;
        Bhi = g_k_hi  + (size_t)z * TT * KD;  Blo = g_k_lo  + (size_t)z * TT * KD;
        C = g_content + (size_t)z * TT * TT;  ldc = TT;  n0 = x * 128;
    } else {
        Ahi = g_qr_hi + (size_t)z * TT * KD;  Alo = g_qr_lo + (size_t)z * TT * KD;
        Bhi = g_rk_hi + (size_t)z * RDP * KD; Blo = g_rk_lo + (size_t)z * RDP * KD;
        C = g_rel + (size_t)z * TT * RDP;     ldc = RDP; n0 = (11 - y + (x - 12)) * 128;
    }
    constexpr int Kt = KD;
    int mw = (wid & 3) * 32, nw = (wid >> 2) * 64;

    float acc[2][NG * 2][4];
    #pragma unroll
    for (int a = 0; a < 2; a++)
        #pragma unroll
        for (int b2 = 0; b2 < NG * 2; b2++)
            #pragma unroll
            for (int c = 0; c < 4; c++) acc[a][b2][c] = 0.f;

    auto issue_stage = [&](int blk, int slot) {
        int k0 = blk * 32;
        uint32_t so = sbase + slot * SS;
        #pragma unroll
        for (int i = tid; i < 128 * 4; i += 256) {
            int r = i >> 2, c = i & 3;
            uint32_t d = so + (((uint32_t)r << 2) + (uint32_t)(c ^ (r & 3))) * 16;
            CP_ASYNC16(d,      Ahi + (size_t)(m0 + r) * Kt + k0 + c * 8);
            CP_ASYNC16(d + AT, Alo + (size_t)(m0 + r) * Kt + k0 + c * 8);
        }
        #pragma unroll
        for (int i = tid; i < 128 * 4; i += 256) {
            int r = i >> 2, c = i & 3;
            uint32_t d = so + 2 * AT + (((uint32_t)r << 2) + (uint32_t)(c ^ (r & 3))) * 16;
            CP_ASYNC16(d,      Bhi + (size_t)(n0 + r) * Kt + k0 + c * 8);
            CP_ASYNC16(d + BT, Blo + (size_t)(n0 + r) * Kt + k0 + c * 8);
        }
    };

    issue_stage(0, 0);
    CP_COMMIT();
    issue_stage(1, 1);
    CP_COMMIT();
    #pragma unroll
    for (int blk = 0; blk < 2; blk++) {
        CP_COMMIT();
        CP_WAIT2();
        __syncthreads();
        uint32_t so = sbase + blk * SS;
        #pragma unroll
        for (int ks = 0; ks < 2; ks++) {
            uint32_t ah[8], al[8];
            #pragma unroll
            for (int fm = 0; fm < 2; fm++) {
                int ra = mw + fm * 16 + (lane & 15);
                int ca = ks * 2 + (lane >> 4);
                uint32_t off = (((uint32_t)ra << 2) + (uint32_t)(ca ^ (ra & 3))) * 16;
                ldm_x4(ah + fm * 4, so + off);
                ldm_x4(al + fm * 4, so + AT + off);
            }
            #pragma unroll
            for (int nt = 0; nt < NG; nt++) {
                int rb = nw + nt * 16 + ((lane >> 4) & 1) * 8 + (lane & 7);
                int cb = ks * 2 + ((lane >> 3) & 1);
                uint32_t offb = (((uint32_t)rb << 2) + (uint32_t)(cb ^ (rb & 3))) * 16;
                uint32_t bh[4], bl[4];
                ldm_x4(bh, so + 2 * AT + offb);
                ldm_x4(bl, so + 2 * AT + BT + offb);
                #pragma unroll
                for (int fm = 0; fm < 2; fm++) {
                    #pragma unroll
                    for (int hf = 0; hf < 2; hf++) {
                        float* cc = acc[fm][nt * 2 + hf];
                        mma_bf16(cc, ah + fm * 4, bh + hf * 2);
                        mma_bf16(cc, ah + fm * 4, bl + hf * 2);
                        mma_bf16(cc, al + fm * 4, bh + hf * 2);
                    }
                }
            }
        }
        __syncthreads();
    }

    int g = lane >> 2, tg = lane & 3;
    #pragma unroll
    for (int fm = 0; fm < 2; fm++) {
        #pragma unroll
        for (int fn = 0; fn < NG * 2; fn++) {
            int n = n0 + nw + fn * 8 + tg * 2;
            int m = m0 + mw + fm * 16 + g;
            float* cc = acc[fm][fn];
            #pragma unroll
            for (int hrow = 0; hrow < 2; hrow++) {
                int mm = m + hrow * 8;
                #pragma unroll
                for (int jj = 0; jj < 2; jj++)
                    C[(size_t)mm * ldc + n + jj] = cc[hrow * 2 + jj];
            }
        }
    }
}

// ========================= generic HMMA GEMM (3-stage) =========================
template <int NT, bool BF16OUT>
__global__ void __launch_bounds__(256)
mma_gemm(const bf16* __restrict__ Ahi, const bf16* __restrict__ Alo, size_t sA,
         const bf16* __restrict__ Bhi, const bf16* __restrict__ Blo, size_t sB,
         float* __restrict__ C, bf16* __restrict__ Chi, bf16* __restrict__ Clo,
         int ldc, size_t sC,
         int M, int Kt, float alpha, const float* __restrict__ bias, int hd) {
    constexpr int AT = 128 * 64;
    constexpr int BT = NT * 64;
    constexpr int SS = 2 * AT + 2 * BT;
    constexpr int WN = NT / 2;
    constexpr int NG = WN / 16;
    extern __shared__ char smem[];
    const uint32_t sbase = smem_to_u32(smem);
    int tid = threadIdx.x, wid = tid >> 5, lane = tid & 31;
    int z = blockIdx.z;
    int m0 = blockIdx.y * 128;
    int n0 = blockIdx.x * NT;
    Ahi += (size_t)z * sA;  Alo += (size_t)z * sA;
    Bhi += (size_t)z * sB;  Blo += (size_t)z * sB;
    int mw = (wid & 3) * 32, nw = (wid >> 2) * WN;

    float acc[2][NG * 2][4];
    #pragma unroll
    for (int a = 0; a < 2; a++)
        #pragma unroll
        for (int b = 0; b < NG * 2; b++)
            #pragma unroll
            for (int c = 0; c < 4; c++) acc[a][b][c] = 0.f;

    int nblk = Kt >> 5;

    auto issue_stage = [&](int blk, int slot) {
        int k0 = blk * 32;
        uint32_t so = sbase + slot * SS;
        #pragma unroll
        for (int i = tid; i < 128 * 4; i += 256) {
            int r = i >> 2, c = i & 3;
            uint32_t d = so + (((uint32_t)r << 2) + (uint32_t)(c ^ (r & 3))) * 16;
            CP_ASYNC16(d,      Ahi + (size_t)(m0 + r) * Kt + k0 + c * 8);
            CP_ASYNC16(d + AT, Alo + (size_t)(m0 + r) * Kt + k0 + c * 8);
        }
        #pragma unroll
        for (int i = tid; i < NT * 4; i += 256) {
            int r = i >> 2, c = i & 3;
            uint32_t d = so + 2 * AT + (((uint32_t)r << 2) + (uint32_t)(c ^ (r & 3))) * 16;
            CP_ASYNC16(d,      Bhi + (size_t)(n0 + r) * Kt + k0 + c * 8);
            CP_ASYNC16(d + BT, Blo + (size_t)(n0 + r) * Kt + k0 + c * 8);
        }
    };

    issue_stage(0, 0);
    CP_COMMIT();
    issue_stage(1, 1);
    CP_COMMIT();
    int slot = 0, nslot = 2;
    for (int blk = 0; blk < nblk; blk++) {
        if (blk + 2 < nblk) issue_stage(blk + 2, nslot);
        CP_COMMIT();
        CP_WAIT2();
        __syncthreads();
        uint32_t so = sbase + slot * SS;
        #pragma unroll
        for (int ks = 0; ks < 2; ks++) {
            uint32_t ah[8], al[8];
            #pragma unroll
            for (int fm = 0; fm < 2; fm++) {
                int ra = mw + fm * 16 + (lane & 15);
                int ca = ks * 2 + (lane >> 4);
                uint32_t off = (((uint32_t)ra << 2) + (uint32_t)(ca ^ (ra & 3))) * 16;
                ldm_x4(ah + fm * 4, so + off);
                ldm_x4(al + fm * 4, so + AT + off);
            }
            #pragma unroll
            for (int nt = 0; nt < NG; nt++) {
                int rb = nw + nt * 16 + ((lane >> 4) & 1) * 8 + (lane & 7);
                int cb = ks * 2 + ((lane >> 3) & 1);
                uint32_t offb = (((uint32_t)rb << 2) + (uint32_t)(cb ^ (rb & 3))) * 16;
                uint32_t bh[4], bl[4];
                ldm_x4(bh, so + 2 * AT + offb);
                ldm_x4(bl, so + 2 * AT + BT + offb);
                #pragma unroll
                for (int fm = 0; fm < 2; fm++) {
                    #pragma unroll
                    for (int hf = 0; hf < 2; hf++) {
                        float* cc = acc[fm][nt * 2 + hf];
                        mma_bf16(cc, ah + fm * 4, bh + hf * 2);
                        mma_bf16(cc, ah + fm * 4, bl + hf * 2);
                        mma_bf16(cc, al + fm * 4, bh + hf * 2);
                    }
                }
            }
        }
        __syncthreads();
        slot = (slot == 2) ? 0 : slot + 1;
        nslot = (nslot == 2) ? 0 : nslot + 1;
    }

    int g = lane >> 2, tg = lane & 3;
    #pragma unroll
    for (int fm = 0; fm < 2; fm++) {
        #pragma unroll
        for (int fn = 0; fn < NG * 2; fn++) {
            int n = n0 + nw + fn * 8 + tg * 2;
            int m = m0 + mw + fm * 16 + g;
            float* cc = acc[fm][fn];
            #pragma unroll
            for (int hrow = 0; hrow < 2; hrow++) {
                int mm = m + hrow * 8;
                if (BF16OUT) {
                    size_t o = hd ? ((size_t)(n / hd) * M + mm) * (size_t)hd + (n % hd)
                                  : (size_t)z * sC + (size_t)mm * ldc + n;
                    bf16 h0, l0, h1, l1;
                    split2(alpha * cc[hrow * 2 + 0], &h0, &l0);
                    split2(alpha * cc[hrow * 2 + 1], &h1, &l1);
                    *(__nv_bfloat162*)(Chi + o) = __nv_bfloat162(h0, h1);
                    *(__nv_bfloat162*)(Clo + o) = __nv_bfloat162(l0, l1);
                } else {
                    #pragma unroll
                    for (int jj = 0; jj < 2; jj++) {
                        int nn = n + jj;
                        float v = alpha * cc[hrow * 2 + jj];
                        if (bias) v += bias[nn];
                        size_t o;
                        if (hd) o = ((size_t)(nn / hd) * M + mm) * (size_t)hd + (nn % hd);
                        else    o = (size_t)z * sC + (size_t)mm * ldc + nn;
                        C[o] = v;
                    }
                }
            }
        }
    }
}

// ========================= combine + softmax + split-P =========================
__global__ void softmax_kernel() {
    __shared__ float s[256];
    int row = blockIdx.x;
    int q = row % TT;
    const float* cont = g_content + (size_t)row * TT;
    const float* rel  = g_rel + (size_t)row * RDP + (TT - 1 - q);
    bf16* phi = g_p_hi + (size_t)row * TT;
    bf16* plo = g_p_lo + (size_t)row * TT;
    int t = threadIdx.x;
    float v[6];
    float mx = -1e30f;
    #pragma unroll
    for (int i = 0; i < 6; i++) {
        int j = t + i * 256;
        v[i] = cont[j] + rel[j];
        mx = fmaxf(mx, v[i]);
    }
    s[t] = mx; __syncthreads();
    for (int o = 128; o > 0; o >>= 1) { if (t < o) s[t] = fmaxf(s[t], s[t + o]); __syncthreads(); }
    mx = s[0]; __syncthreads();
    float sum = 0.f;
    #pragma unroll
    for (int i = 0; i < 6; i++) { v[i] = expf(v[i] - mx); sum += v[i]; }
    s[t] = sum; __syncthreads();
    for (int o = 128; o > 0; o >>= 1) { if (t < o) s[t] += s[t + o]; __syncthreads(); }
    float inv = 1.0f / s[0];
    #pragma unroll
    for (int i = 0; i < 6; i++) {
        int j = t + i * 256;
        split2(v[i] * inv, phi + j, plo + j);
    }
}

// ========================= launch =========================
static void* dev_ptr(const void* symbol) {
    void* p = nullptr;
    cudaGetSymbolAddress(&p, symbol);
    return p;
}

extern "C" void kernel_launch(void* const* d_in, const int* in_sizes, int n_in,
                              void* d_out, int out_size) {
    const float* inputs = (const float*)d_in[0];
    const float* Wq  = (const float*)d_in[1];
    const float* Wk  = (const float*)d_in[2];
    const float* Wv  = (const float*)d_in[3];
    const float* Wrk = (const float*)d_in[4];
    const float* rwb = (const float*)d_in[5];
    const float* rrb = (const float*)d_in[6];
    const float* We  = (const float*)d_in[7];
    const float* be  = (const float*)d_in[8];
    float* out = (float*)d_out;

    const int SM128 = 3 * (2 * 128 * 64 + 2 * 128 * 64);  // 98304
    const int SM64  = 3 * (2 * 128 * 64 + 2 * 64 * 64);   // 73728
    cudaFuncSetAttribute((const void*)mma_gemm<64, false>,  cudaFuncAttributeMaxDynamicSharedMemorySize, SM64);
    cudaFuncSetAttribute((const void*)mma_gemm<64, true>,   cudaFuncAttributeMaxDynamicSharedMemorySize, SM64);
    cudaFuncSetAttribute((const void*)proj_gemm,            cudaFuncAttributeMaxDynamicSharedMemorySize, SM128);
    cudaFuncSetAttribute((const void*)logits_gemm,          cudaFuncAttributeMaxDynamicSharedMemorySize, SM128);

    float* pv = (float*)dev_ptr(g_v);
    float* prkf = (float*)dev_ptr(g_rkf);
    bf16* pe_hi = (bf16*)dev_ptr(g_pe_hi);   bf16* pe_lo = (bf16*)dev_ptr(g_pe_lo);
    bf16* wrkT_hi = (bf16*)dev_ptr(g_wrkT_hi); bf16* wrkT_lo = (bf16*)dev_ptr(g_wrkT_lo);
    bf16* weT_hi = (bf16*)dev_ptr(g_weT_hi); bf16* weT_lo = (bf16*)dev_ptr(g_weT_lo);
    bf16* vT_hi = (bf16*)dev_ptr(g_vT_hi); bf16* vT_lo = (bf16*)dev_ptr(g_vT_lo);
    bf16* p_hi = (bf16*)dev_ptr(g_p_hi); bf16* p_lo = (bf16*)dev_ptr(g_p_lo);
    bf16* at_hi = (bf16*)dev_ptr(g_at_hi); bf16* at_lo = (bf16*)dev_ptr(g_at_lo);

    dim3 tb(32, 8);

    // 1: gamma features
    pf_gamma_raw_kernel<<<(RD * NB + 255) / 256, 256>>>();
    // 2: fused prep (input split + all weight transpose-splits)
    prep_kernel<<<8544, 256>>>(inputs, Wq, Wk, Wv, We, Wrk);
    // 3: gamma max
    pf_max_kernel<<<1, 1024>>>();
    // 4: fused V + QK projections (NT=128, 240 CTAs, 2 CTAs/SM, single wave) — ncu slot
    proj_gemm<<<240, 256, SM128>>>();
    // 5: positional feature build (needs gmax)
    pf_build_kernel<<<(RDP * 96 + 255) / 256, 256>>>();
    // 6: RK projection (K=192) -> head-major fp32
    mma_gemm<64, false><<<dim3(8, 24, 1), 256, SM64>>>(pe_hi, pe_lo, 0, wrkT_hi, wrkT_lo, 0,
        prkf, nullptr, nullptr, 0, 0, RDP, 192, 1.0f, nullptr, KD);
    // 7: fused glue: qw/qr (raw biases), k split, rk split
    fuse_split_kernel<<<(2 * QKSZ + RKSZ + 255) / 256, 256>>>(rwb, rrb);
    // 8: vT split
    tsplit_kernel<<<dim3(VD / 32, TT / 32, HH), tb>>>(pv, vT_hi, vT_lo, TT, VD,
        (size_t)TT * VD, (size_t)VD * TT);
    // 9: combined content + rel logits (K=64, 2400 CTAs)
    logits_gemm<<<dim3(25, 12, HH), 256, SM128>>>();
    // 10: combine + softmax -> P (bf16 hi/lo)
    softmax_kernel<<<HH * TT, 256>>>();
    // 11: P @ V (K=1536) -> attn split bf16 directly
    mma_gemm<64, true><<<dim3(3, 12, HH), 256, SM64>>>(p_hi, p_lo, (size_t)TT * TT,
        vT_hi, vT_lo, (size_t)VD * TT, nullptr, at_hi, at_lo, CDIM, (size_t)VD,
        TT, TT, 1.0f, nullptr, 0);
    // 12: out = attn @ We + be (K=1536, NT=64)
    mma_gemm<64, false><<<dim3(24, 12, 1), 256, SM64>>>(at_hi, at_lo, 0, weT_hi, weT_lo, 0,
        out, nullptr, nullptr, CDIM, 0, TT, CDIM, 1.0f, be, 0);
}

// round 16
// speedup vs baseline: 1.0939x; 1.0555x over previous
#include <cuda_runtime.h>
#include <cuda_bf16.h>
#include <math.h>
#include <stdint.h>

#define TT   1536
#define CDIM 1536
#define HH   8
#define KD   64
#define VD   192
#define RD   3071
#define RDP  3072
#define NB   32

typedef __nv_bfloat16 bf16;

// ========================= helpers =========================
__device__ __forceinline__ uint32_t smem_to_u32(const void* p) {
    uint32_t a;
    asm("{ .reg .u64 t; cvta.to.shared.u64 t, %1; cvt.u32.u64 %0, t; }" : "=r"(a) : "l"(p));
    return a;
}
#define CP_ASYNC16(dst, src) \
    asm volatile("cp.async.cg.shared.global [%0], [%1], 16;" :: "r"(dst), "l"(src))
#define CP_COMMIT() asm volatile("cp.async.commit_group;" ::: "memory")
#define CP_WAIT2()  asm volatile("cp.async.wait_group 2;" ::: "memory")

__device__ __forceinline__ void ldm_x4(uint32_t* r, uint32_t addr) {
    asm volatile("ldmatrix.sync.aligned.m8n8.x4.shared.b16 {%0,%1,%2,%3}, [%4];"
        : "=r"(r[0]), "=r"(r[1]), "=r"(r[2]), "=r"(r[3]) : "r"(addr));
}
__device__ __forceinline__ void mma_bf16(float* c, const uint32_t* a, const uint32_t* b) {
    asm volatile("mma.sync.aligned.m16n8k16.row.col.f32.bf16.bf16.f32 "
        "{%0,%1,%2,%3}, {%4,%5,%6,%7}, {%8,%9}, {%0,%1,%2,%3};"
        : "+f"(c[0]), "+f"(c[1]), "+f"(c[2]), "+f"(c[3])
        : "r"(a[0]), "r"(a[1]), "r"(a[2]), "r"(a[3]), "r"(b[0]), "r"(b[1]));
}

// ========================= scratch =========================
__device__ float g_gprobs[RD * NB];
__device__ float g_gmax;
__device__ __align__(16) bf16 g_pe_hi[RDP * 192], g_pe_lo[RDP * 192];
__device__ __align__(16) bf16 g_wqkT_hi[1024 * CDIM], g_wqkT_lo[1024 * CDIM];
__device__ __align__(16) bf16 g_wvT_hi[CDIM * CDIM], g_wvT_lo[CDIM * CDIM];
__device__ __align__(16) bf16 g_weT_hi[CDIM * CDIM], g_weT_lo[CDIM * CDIM];
__device__ __align__(16) bf16 g_wrkT_hi[512 * 192], g_wrkT_lo[512 * 192];
__device__ __align__(16) bf16 g_in_hi[TT * CDIM], g_in_lo[TT * CDIM];
__device__ __align__(16) float g_qk[2 * HH * TT * KD];   // heads 0-7: q (pre-scaled), 8-15: k
__device__ __align__(16) float g_v[HH * TT * VD];
__device__ __align__(16) float g_rkf[HH * RDP * KD];
__device__ __align__(16) bf16 g_qw_hi[HH * TT * KD], g_qw_lo[HH * TT * KD];
__device__ __align__(16) bf16 g_qr_hi[HH * TT * KD], g_qr_lo[HH * TT * KD];
__device__ __align__(16) bf16 g_k_hi[HH * TT * KD], g_k_lo[HH * TT * KD];
__device__ __align__(16) bf16 g_rk_hi[HH * RDP * KD], g_rk_lo[HH * RDP * KD];
__device__ __align__(16) bf16 g_vT_hi[HH * VD * TT], g_vT_lo[HH * VD * TT];
__device__ __align__(16) float g_content[(size_t)HH * TT * TT];
__device__ __align__(16) float g_rel[(size_t)HH * TT * RDP];
__device__ __align__(16) bf16 g_p_hi[(size_t)HH * TT * TT], g_p_lo[(size_t)HH * TT * TT];
__device__ __align__(16) bf16 g_at_hi[TT * CDIM], g_at_lo[TT * CDIM];

__device__ __forceinline__ void split2(float x, bf16* hi, bf16* lo) {
    bf16 h = __float2bfloat16(x);
    *hi = h;
    *lo = __float2bfloat16(x - __bfloat162float(h));
}

// ========================= positional features =========================
__global__ void pf_gamma_raw_kernel() {
    int idx = blockIdx.x * blockDim.x + threadIdx.x;
    if (idx >= RD * NB) return;
    int r = idx / NB, i = idx % NB;
    double x    = fabs((double)(r - (TT - 1)));
    double mean = 48.0 * (i + 1);
    double conc = (mean / 24.0) * (mean / 24.0);
    double rate = mean / 576.0;
    double lu   = (conc - 1.0) * log(x) - rate * x;
    double ln   = lgamma(conc) - conc * log(rate);
    g_gprobs[idx] = (float)exp(lu - ln) + 1e-8f;
}

__global__ void pf_max_kernel() {
    __shared__ float s[1024];
    int t = threadIdx.x;
    float m = 0.f;
    for (int i = t; i < RD * NB; i += 1024) m = fmaxf(m, g_gprobs[i]);
    s[t] = m; __syncthreads();
    for (int o = 512; o > 0; o >>= 1) { if (t < o) s[t] = fmaxf(s[t], s[t + o]); __syncthreads(); }
    if (t == 0) g_gmax = s[0];
}

__global__ void pf_build_kernel() {
    int idx = blockIdx.x * blockDim.x + threadIdx.x;
    if (idx >= RDP * 96) return;
    int r = idx / 96, i = idx % 96;
    float v1 = 0.f, v2 = 0.f;
    if (r < RD) {
        float p  = (float)(r - (TT - 1));
        float ap = fabsf(p);
        float val;
        if (i < 32) {
            double mr = log(1536.0) / log(2.0);
            double hl = pow(2.0, 3.0 + (double)i * (mr - 3.0) / 31.0);
            val = expf(-(float)(0.6931471805599453 / hl) * ap);
        } else if (i < 64) {
            float cw = exp2f((float)(i - 32 + 1)) - 1.0f;
            val = (cw > ap) ? 1.0f : 0.0f;
        } else {
            val = g_gprobs[r * NB + (i - 64)] / g_gmax;
        }
        float sg = (p > 0.f) ? 1.f : ((p < 0.f) ? -1.f : 0.f);
        v1 = val; v2 = sg * val;
    }
    split2(v1, &g_pe_hi[r * 192 + i],      &g_pe_lo[r * 192 + i]);
    split2(v2, &g_pe_hi[r * 192 + 96 + i], &g_pe_lo[r * 192 + 96 + i]);
}

// ========================= fused prep: input split + all weight transpose-splits =========================
__global__ void prep_kernel(const float* __restrict__ inputs,
                            const float* __restrict__ Wq, const float* __restrict__ Wk,
                            const float* __restrict__ Wv, const float* __restrict__ We,
                            const float* __restrict__ Wrk) {
    __shared__ float t[32][33];
    int b = blockIdx.x;
    int tid = threadIdx.x;
    if (b >= 6240) {
        int i = (b - 6240) * 256 + tid;
        float4 v = reinterpret_cast<const float4*>(inputs)[i];
        bf16 h0, l0, h1, l1, h2, l2, h3, l3;
        split2(v.x, &h0, &l0); split2(v.y, &h1, &l1);
        split2(v.z, &h2, &l2); split2(v.w, &h3, &l3);
        __nv_bfloat162* hp = reinterpret_cast<__nv_bfloat162*>(g_in_hi + 4 * (size_t)i);
        __nv_bfloat162* lp = reinterpret_cast<__nv_bfloat162*>(g_in_lo + 4 * (size_t)i);
        hp[0] = __nv_bfloat162(h0, h1); hp[1] = __nv_bfloat162(h2, h3);
        lp[0] = __nv_bfloat162(l0, l1); lp[1] = __nv_bfloat162(l2, l3);
        return;
    }
    const float* in;
    bf16 *hi, *lo;
    int Cc, Rout, tidx;
    float scale = 1.0f;
    if (b < 2304)      { in = Wv;  hi = g_wvT_hi;  lo = g_wvT_lo;  Cc = CDIM; Rout = CDIM; tidx = b; }
    else if (b < 3072) { in = Wq;  hi = g_wqkT_hi; lo = g_wqkT_lo; Cc = 512;  Rout = CDIM; tidx = b - 2304; scale = 0.125f; }
    else if (b < 3840) { in = Wk;  hi = g_wqkT_hi + 512 * CDIM; lo = g_wqkT_lo + 512 * CDIM;
                         Cc = 512;  Rout = CDIM; tidx = b - 3072; }
    else if (b < 6144) { in = We;  hi = g_weT_hi;  lo = g_weT_lo;  Cc = CDIM; Rout = CDIM; tidx = b - 3840; }
    else               { in = Wrk; hi = g_wrkT_hi; lo = g_wrkT_lo; Cc = 512;  Rout = 192;  tidx = b - 6144; }
    int ntc = Cc / 32;
    int c0 = (tidx % ntc) * 32, r0 = (tidx / ntc) * 32;
    int tx = tid & 31, ty = tid >> 5;
    #pragma unroll
    for (int i = 0; i < 32; i += 8)
        t[ty + i][tx] = in[(size_t)(r0 + ty + i) * Cc + c0 + tx];
    __syncthreads();
    #pragma unroll
    for (int i = 0; i < 32; i += 8) {
        size_t o = (size_t)(c0 + ty + i) * Rout + r0 + tx;
        split2(t[tx][ty + i] * scale, hi + o, lo + o);
    }
}

// vT split
__global__ void tsplit_kernel(const float* __restrict__ in, bf16* __restrict__ hi,
                              bf16* __restrict__ lo, int R, int Cc, size_t sIn, size_t sOut) {
    __shared__ float t[32][33];
    int z = blockIdx.z;
    in += (size_t)z * sIn;
    int c0 = blockIdx.x * 32, r0 = blockIdx.y * 32;
    int tx = threadIdx.x, ty = threadIdx.y;
    #pragma unroll
    for (int i = 0; i < 32; i += 8)
        t[ty + i][tx] = in[(size_t)(r0 + ty + i) * Cc + c0 + tx];
    __syncthreads();
    #pragma unroll
    for (int i = 0; i < 32; i += 8) {
        size_t o = (size_t)z * sOut + (size_t)(c0 + ty + i) * R + r0 + tx;
        split2(t[tx][ty + i], hi + o, lo + o);
    }
}

// fused: q+bias splits, k split, rk split
#define QKSZ (HH * TT * KD)
#define RKSZ (HH * RDP * KD)
__global__ void fuse_split_kernel(const float* __restrict__ rwb, const float* __restrict__ rrb) {
    int idx = blockIdx.x * blockDim.x + threadIdx.x;
    if (idx < QKSZ) {
        int h = idx / (TT * KD);
        int d = idx & (KD - 1);
        float qv = g_qk[idx];     // already scaled by 1/8 (baked into Wq)
        split2(qv + rwb[h * KD + d], &g_qw_hi[idx], &g_qw_lo[idx]);
        split2(qv + rrb[h * KD + d], &g_qr_hi[idx], &g_qr_lo[idx]);
    } else if (idx < 2 * QKSZ) {
        int i = idx - QKSZ;
        split2(g_qk[QKSZ + i], &g_k_hi[i], &g_k_lo[i]);
    } else if (idx < 2 * QKSZ + RKSZ) {
        int i = idx - 2 * QKSZ;
        split2(g_rkf[i], &g_rk_hi[i], &g_rk_lo[i]);
    }
}

// ========================= fused V + QK projection GEMM (NT=128, 240 CTAs, 2 CTAs/SM) =========================
__global__ void __launch_bounds__(256, 2)
proj_gemm() {
    constexpr int AT = 128 * 64;
    constexpr int BT = 128 * 64;
    constexpr int SS = 2 * AT + 2 * BT;
    constexpr int NG = 4;
    extern __shared__ char smem[];
    const uint32_t sbase = smem_to_u32(smem);
    int tid = threadIdx.x, wid = tid >> 5, lane = tid & 31;
    int b = blockIdx.x;

    const bf16 *Bhi, *Blo;
    float* C;
    int hd, m0, n0;
    if (b < 144) {                    // V projection: N=1536 -> 12 n-tiles
        n0 = (b % 12) * 128;  m0 = (b / 12) * 128;
        Bhi = g_wvT_hi;  Blo = g_wvT_lo;  C = g_v;  hd = VD;
    } else {                          // QK projection: N=1024 -> 8 n-tiles
        int t = b - 144;
        n0 = (t % 8) * 128;  m0 = (t / 8) * 128;
        Bhi = g_wqkT_hi;  Blo = g_wqkT_lo;  C = g_qk;  hd = KD;
    }
    const bf16* Ahi = g_in_hi;
    const bf16* Alo = g_in_lo;
    constexpr int Kt = CDIM, M = TT;
    int mw = (wid & 3) * 32, nw = (wid >> 2) * 64;

    float acc[2][NG * 2][4];
    #pragma unroll
    for (int a = 0; a < 2; a++)
        #pragma unroll
        for (int b2 = 0; b2 < NG * 2; b2++)
            #pragma unroll
            for (int c = 0; c < 4; c++) acc[a][b2][c] = 0.f;

    constexpr int nblk = Kt >> 5;

    auto issue_stage = [&](int blk, int slot) {
        int k0 = blk * 32;
        uint32_t so = sbase + slot * SS;
        #pragma unroll
        for (int i = tid; i < 128 * 4; i += 256) {
            int r = i >> 2, c = i & 3;
            uint32_t d = so + (((uint32_t)r << 2) + (uint32_t)(c ^ (r & 3))) * 16;
            CP_ASYNC16(d,      Ahi + (size_t)(m0 + r) * Kt + k0 + c * 8);
            CP_ASYNC16(d + AT, Alo + (size_t)(m0 + r) * Kt + k0 + c * 8);
        }
        #pragma unroll
        for (int i = tid; i < 128 * 4; i += 256) {
            int r = i >> 2, c = i & 3;
            uint32_t d = so + 2 * AT + (((uint32_t)r << 2) + (uint32_t)(c ^ (r & 3))) * 16;
            CP_ASYNC16(d,      Bhi + (size_t)(n0 + r) * Kt + k0 + c * 8);
            CP_ASYNC16(d + BT, Blo + (size_t)(n0 + r) * Kt + k0 + c * 8);
        }
    };

    issue_stage(0, 0);
    CP_COMMIT();
    issue_stage(1, 1);
    CP_COMMIT();
    int slot = 0, nslot = 2;
    for (int blk = 0; blk < nblk; blk++) {
        if (blk + 2 < nblk) issue_stage(blk + 2, nslot);
        CP_COMMIT();
        CP_WAIT2();
        __syncthreads();
        uint32_t so = sbase + slot * SS;
        #pragma unroll
        for (int ks = 0; ks < 2; ks++) {
            uint32_t ah[8], al[8];
            #pragma unroll
            for (int fm = 0; fm < 2; fm++) {
                int ra = mw + fm * 16 + (lane & 15);
                int ca = ks * 2 + (lane >> 4);
                uint32_t off = (((uint32_t)ra << 2) + (uint32_t)(ca ^ (ra & 3))) * 16;
                ldm_x4(ah + fm * 4, so + off);
                ldm_x4(al + fm * 4, so + AT + off);
            }
            #pragma unroll
            for (int nt = 0; nt < NG; nt++) {
                int rb = nw + nt * 16 + ((lane >> 4) & 1) * 8 + (lane & 7);
                int cb = ks * 2 + ((lane >> 3) & 1);
                uint32_t offb = (((uint32_t)rb << 2) + (uint32_t)(cb ^ (rb & 3))) * 16;
                uint32_t bh[4], bl[4];
                ldm_x4(bh, so + 2 * AT + offb);
                ldm_x4(bl, so + 2 * AT + BT + offb);
                #pragma unroll
                for (int fm = 0; fm < 2; fm++) {
                    #pragma unroll
                    for (int hf = 0; hf < 2; hf++) {
                        float* cc = acc[fm][nt * 2 + hf];
                        mma_bf16(cc, ah + fm * 4, bh + hf * 2);
                        mma_bf16(cc, ah + fm * 4, bl + hf * 2);
                        mma_bf16(cc, al + fm * 4, bh + hf * 2);
                    }
                }
            }
        }
        __syncthreads();
        slot = (slot == 2) ? 0 : slot + 1;
        nslot = (nslot == 2) ? 0 : nslot + 1;
    }

    int g = lane >> 2, tg = lane & 3;
    #pragma unroll
    for (int fm = 0; fm < 2; fm++) {
        #pragma unroll
        for (int fn = 0; fn < NG * 2; fn++) {
            int n = n0 + nw + fn * 8 + tg * 2;
            int m = m0 + mw + fm * 16 + g;
            float* cc = acc[fm][fn];
            #pragma unroll
            for (int hrow = 0; hrow < 2; hrow++) {
                int mm = m + hrow * 8;
                #pragma unroll
                for (int jj = 0; jj < 2; jj++) {
                    int nn = n + jj;
                    size_t o = ((size_t)(nn / hd) * M + mm) * (size_t)hd + (nn % hd);
                    C[o] = cc[hrow * 2 + jj];
                }
            }
        }
    }
}

// ========================= combined logits GEMM (content + banded rel, NT=128, 2 CTAs/SM) =========================
__global__ void __launch_bounds__(256, 2)
logits_gemm() {
    constexpr int AT = 128 * 64;
    constexpr int BT = 128 * 64;
    constexpr int SS = 2 * AT + 2 * BT;
    constexpr int NG = 4;
    extern __shared__ char smem[];
    const uint32_t sbase = smem_to_u32(smem);
    int tid = threadIdx.x, wid = tid >> 5, lane = tid & 31;
    int z = blockIdx.z, y = blockIdx.y, x = blockIdx.x;
    int m0 = y * 128;
    const bf16 *Ahi, *Alo, *Bhi, *Blo;
    float* C;
    int ldc, n0;
    if (x < 12) {
        Ahi = g_qw_hi + (size_t)z * TT * KD;  Alo = g_qw_lo + (size_t)z * TT * KD;
        Bhi = g_k_hi  + (size_t)z * TT * KD;  Blo = g_k_lo  + (size_t)z * TT * KD;
        C = g_content + (size_t)z * TT * TT;  ldc = TT;  n0 = x * 128;
    } else {
        Ahi = g_qr_hi + (size_t)z * TT * KD;  Alo = g_qr_lo + (size_t)z * TT * KD;
        Bhi = g_rk_hi + (size_t)z * RDP * KD; Blo = g_rk_lo + (size_t)z * RDP * KD;
        C = g_rel + (size_t)z * TT * RDP;     ldc = RDP; n0 = (11 - y + (x - 12)) * 128;
    }
    constexpr int Kt = KD;
    int mw = (wid & 3) * 32, nw = (wid >> 2) * 64;

    float acc[2][NG * 2][4];
    #pragma unroll
    for (int a = 0; a < 2; a++)
        #pragma unroll
        for (int b2 = 0; b2 < NG * 2; b2++)
            #pragma unroll
            for (int c = 0; c < 4; c++) acc[a][b2][c] = 0.f;

    auto issue_stage = [&](int blk, int slot) {
        int k0 = blk * 32;
        uint32_t so = sbase + slot * SS;
        #pragma unroll
        for (int i = tid; i < 128 * 4; i += 256) {
            int r = i >> 2, c = i & 3;
            uint32_t d = so + (((uint32_t)r << 2) + (uint32_t)(c ^ (r & 3))) * 16;
            CP_ASYNC16(d,      Ahi + (size_t)(m0 + r) * Kt + k0 + c * 8);
            CP_ASYNC16(d + AT, Alo + (size_t)(m0 + r) * Kt + k0 + c * 8);
        }
        #pragma unroll
        for (int i = tid; i < 128 * 4; i += 256) {
            int r = i >> 2, c = i & 3;
            uint32_t d = so + 2 * AT + (((uint32_t)r << 2) + (uint32_t)(c ^ (r & 3))) * 16;
            CP_ASYNC16(d,      Bhi + (size_t)(n0 + r) * Kt + k0 + c * 8);
            CP_ASYNC16(d + BT, Blo + (size_t)(n0 + r) * Kt + k0 + c * 8);
        }
    };

    issue_stage(0, 0);
    CP_COMMIT();
    issue_stage(1, 1);
    CP_COMMIT();
    #pragma unroll
    for (int blk = 0; blk < 2; blk++) {
        CP_COMMIT();
        CP_WAIT2();
        __syncthreads();
        uint32_t so = sbase + blk * SS;
        #pragma unroll
        for (int ks = 0; ks < 2; ks++) {
            uint32_t ah[8], al[8];
            #pragma unroll
            for (int fm = 0; fm < 2; fm++) {
                int ra = mw + fm * 16 + (lane & 15);
                int ca = ks * 2 + (lane >> 4);
                uint32_t off = (((uint32_t)ra << 2) + (uint32_t)(ca ^ (ra & 3))) * 16;
                ldm_x4(ah + fm * 4, so + off);
                ldm_x4(al + fm * 4, so + AT + off);
            }
            #pragma unroll
            for (int nt = 0; nt < NG; nt++) {
                int rb = nw + nt * 16 + ((lane >> 4) & 1) * 8 + (lane & 7);
                int cb = ks * 2 + ((lane >> 3) & 1);
                uint32_t offb = (((uint32_t)rb << 2) + (uint32_t)(cb ^ (rb & 3))) * 16;
                uint32_t bh[4], bl[4];
                ldm_x4(bh, so + 2 * AT + offb);
                ldm_x4(bl, so + 2 * AT + BT + offb);
                #pragma unroll
                for (int fm = 0; fm < 2; fm++) {
                    #pragma unroll
                    for (int hf = 0; hf < 2; hf++) {
                        float* cc = acc[fm][nt * 2 + hf];
                        mma_bf16(cc, ah + fm * 4, bh + hf * 2);
                        mma_bf16(cc, ah + fm * 4, bl + hf * 2);
                        mma_bf16(cc, al + fm * 4, bh + hf * 2);
                    }
                }
            }
        }
        __syncthreads();
    }

    int g = lane >> 2, tg = lane & 3;
    #pragma unroll
    for (int fm = 0; fm < 2; fm++) {
        #pragma unroll
        for (int fn = 0; fn < NG * 2; fn++) {
            int n = n0 + nw + fn * 8 + tg * 2;
            int m = m0 + mw + fm * 16 + g;
            float* cc = acc[fm][fn];
            #pragma unroll
            for (int hrow = 0; hrow < 2; hrow++) {
                int mm = m + hrow * 8;
                #pragma unroll
                for (int jj = 0; jj < 2; jj++)
                    C[(size_t)mm * ldc + n + jj] = cc[hrow * 2 + jj];
            }
        }
    }
}

// ========================= generic HMMA GEMM (3-stage) =========================
template <int NT, bool BF16OUT>
__global__ void __launch_bounds__(256)
mma_gemm(const bf16* __restrict__ Ahi, const bf16* __restrict__ Alo, size_t sA,
         const bf16* __restrict__ Bhi, const bf16* __restrict__ Blo, size_t sB,
         float* __restrict__ C, bf16* __restrict__ Chi, bf16* __restrict__ Clo,
         int ldc, size_t sC,
         int M, int Kt, float alpha, const float* __restrict__ bias, int hd) {
    constexpr int AT = 128 * 64;
    constexpr int BT = NT * 64;
    constexpr int SS = 2 * AT + 2 * BT;
    constexpr int WN = NT / 2;
    constexpr int NG = WN / 16;
    extern __shared__ char smem[];
    const uint32_t sbase = smem_to_u32(smem);
    int tid = threadIdx.x, wid = tid >> 5, lane = tid & 31;
    int z = blockIdx.z;
    int m0 = blockIdx.y * 128;
    int n0 = blockIdx.x * NT;
    Ahi += (size_t)z * sA;  Alo += (size_t)z * sA;
    Bhi += (size_t)z * sB;  Blo += (size_t)z * sB;
    int mw = (wid & 3) * 32, nw = (wid >> 2) * WN;

    float acc[2][NG * 2][4];
    #pragma unroll
    for (int a = 0; a < 2; a++)
        #pragma unroll
        for (int b = 0; b < NG * 2; b++)
            #pragma unroll
            for (int c = 0; c < 4; c++) acc[a][b][c] = 0.f;

    int nblk = Kt >> 5;

    auto issue_stage = [&](int blk, int slot) {
        int k0 = blk * 32;
        uint32_t so = sbase + slot * SS;
        #pragma unroll
        for (int i = tid; i < 128 * 4; i += 256) {
            int r = i >> 2, c = i & 3;
            uint32_t d = so + (((uint32_t)r << 2) + (uint32_t)(c ^ (r & 3))) * 16;
            CP_ASYNC16(d,      Ahi + (size_t)(m0 + r) * Kt + k0 + c * 8);
            CP_ASYNC16(d + AT, Alo + (size_t)(m0 + r) * Kt + k0 + c * 8);
        }
        #pragma unroll
        for (int i = tid; i < NT * 4; i += 256) {
            int r = i >> 2, c = i & 3;
            uint32_t d = so + 2 * AT + (((uint32_t)r << 2) + (uint32_t)(c ^ (r & 3))) * 16;
            CP_ASYNC16(d,      Bhi + (size_t)(n0 + r) * Kt + k0 + c * 8);
            CP_ASYNC16(d + BT, Blo + (size_t)(n0 + r) * Kt + k0 + c * 8);
        }
    };

    issue_stage(0, 0);
    CP_COMMIT();
    issue_stage(1, 1);
    CP_COMMIT();
    int slot = 0, nslot = 2;
    for (int blk = 0; blk < nblk; blk++) {
        if (blk + 2 < nblk) issue_stage(blk + 2, nslot);
        CP_COMMIT();
        CP_WAIT2();
        __syncthreads();
        uint32_t so = sbase + slot * SS;
        #pragma unroll
        for (int ks = 0; ks < 2; ks++) {
            uint32_t ah[8], al[8];
            #pragma unroll
            for (int fm = 0; fm < 2; fm++) {
                int ra = mw + fm * 16 + (lane & 15);
                int ca = ks * 2 + (lane >> 4);
                uint32_t off = (((uint32_t)ra << 2) + (uint32_t)(ca ^ (ra & 3))) * 16;
                ldm_x4(ah + fm * 4, so + off);
                ldm_x4(al + fm * 4, so + AT + off);
            }
            #pragma unroll
            for (int nt = 0; nt < NG; nt++) {
                int rb = nw + nt * 16 + ((lane >> 4) & 1) * 8 + (lane & 7);
                int cb = ks * 2 + ((lane >> 3) & 1);
                uint32_t offb = (((uint32_t)rb << 2) + (uint32_t)(cb ^ (rb & 3))) * 16;
                uint32_t bh[4], bl[4];
                ldm_x4(bh, so + 2 * AT + offb);
                ldm_x4(bl, so + 2 * AT + BT + offb);
                #pragma unroll
                for (int fm = 0; fm < 2; fm++) {
                    #pragma unroll
                    for (int hf = 0; hf < 2; hf++) {
                        float* cc = acc[fm][nt * 2 + hf];
                        mma_bf16(cc, ah + fm * 4, bh + hf * 2);
                        mma_bf16(cc, ah + fm * 4, bl + hf * 2);
                        mma_bf16(cc, al + fm * 4, bh + hf * 2);
                    }
                }
            }
        }
        __syncthreads();
        slot = (slot == 2) ? 0 : slot + 1;
        nslot = (nslot == 2) ? 0 : nslot + 1;
    }

    int g = lane >> 2, tg = lane & 3;
    #pragma unroll
    for (int fm = 0; fm < 2; fm++) {
        #pragma unroll
        for (int fn = 0; fn < NG * 2; fn++) {
            int n = n0 + nw + fn * 8 + tg * 2;
            int m = m0 + mw + fm * 16 + g;
            float* cc = acc[fm][fn];
            #pragma unroll
            for (int hrow = 0; hrow < 2; hrow++) {
                int mm = m + hrow * 8;
                if (BF16OUT) {
                    size_t o = hd ? ((size_t)(n / hd) * M + mm) * (size_t)hd + (n % hd)
                                  : (size_t)z * sC + (size_t)mm * ldc + n;
                    bf16 h0, l0, h1, l1;
                    split2(alpha * cc[hrow * 2 + 0], &h0, &l0);
                    split2(alpha * cc[hrow * 2 + 1], &h1, &l1);
                    *(__nv_bfloat162*)(Chi + o) = __nv_bfloat162(h0, h1);
                    *(__nv_bfloat162*)(Clo + o) = __nv_bfloat162(l0, l1);
                } else {
                    #pragma unroll
                    for (int jj = 0; jj < 2; jj++) {
                        int nn = n + jj;
                        float v = alpha * cc[hrow * 2 + jj];
                        if (bias) v += bias[nn];
                        size_t o;
                        if (hd) o = ((size_t)(nn / hd) * M + mm) * (size_t)hd + (nn % hd);
                        else    o = (size_t)z * sC + (size_t)mm * ldc + nn;
                        C[o] = v;
                    }
                }
            }
        }
    }
}

// ========================= combine + softmax + split-P =========================
__global__ void softmax_kernel() {
    __shared__ float s[256];
    int row = blockIdx.x;
    int q = row % TT;
    const float* cont = g_content + (size_t)row * TT;
    const float* rel  = g_rel + (size_t)row * RDP + (TT - 1 - q);
    bf16* phi = g_p_hi + (size_t)row * TT;
    bf16* plo = g_p_lo + (size_t)row * TT;
    int t = threadIdx.x;
    float v[6];
    float mx = -1e30f;
    #pragma unroll
    for (int i = 0; i < 6; i++) {
        int j = t + i * 256;
        v[i] = cont[j] + rel[j];
        mx = fmaxf(mx, v[i]);
    }
    s[t] = mx; __syncthreads();
    for (int o = 128; o > 0; o >>= 1) { if (t < o) s[t] = fmaxf(s[t], s[t + o]); __syncthreads(); }
    mx = s[0]; __syncthreads();
    float sum = 0.f;
    #pragma unroll
    for (int i = 0; i < 6; i++) { v[i] = expf(v[i] - mx); sum += v[i]; }
    s[t] = sum; __syncthreads();
    for (int o = 128; o > 0; o >>= 1) { if (t < o) s[t] += s[t + o]; __syncthreads(); }
    float inv = 1.0f / s[0];
    #pragma unroll
    for (int i = 0; i < 6; i++) {
        int j = t + i * 256;
        split2(v[i] * inv, phi + j, plo + j);
    }
}

// ========================= launch =========================
static void* dev_ptr(const void* symbol) {
    void* p = nullptr;
    cudaGetSymbolAddress(&p, symbol);
    return p;
}

extern "C" void kernel_launch(void* const* d_in, const int* in_sizes, int n_in,
                              void* d_out, int out_size) {
    const float* inputs = (const float*)d_in[0];
    const float* Wq  = (const float*)d_in[1];
    const float* Wk  = (const float*)d_in[2];
    const float* Wv  = (const float*)d_in[3];
    const float* Wrk = (const float*)d_in[4];
    const float* rwb = (const float*)d_in[5];
    const float* rrb = (const float*)d_in[6];
    const float* We  = (const float*)d_in[7];
    const float* be  = (const float*)d_in[8];
    float* out = (float*)d_out;

    const int SM128 = 3 * (2 * 128 * 64 + 2 * 128 * 64);  // 98304
    const int SM64  = 3 * (2 * 128 * 64 + 2 * 64 * 64);   // 73728
    cudaFuncSetAttribute((const void*)mma_gemm<64, false>,  cudaFuncAttributeMaxDynamicSharedMemorySize, SM64);
    cudaFuncSetAttribute((const void*)mma_gemm<64, true>,   cudaFuncAttributeMaxDynamicSharedMemorySize, SM64);
    cudaFuncSetAttribute((const void*)proj_gemm,            cudaFuncAttributeMaxDynamicSharedMemorySize, SM128);
    cudaFuncSetAttribute((const void*)logits_gemm,          cudaFuncAttributeMaxDynamicSharedMemorySize, SM128);

    float* pv = (float*)dev_ptr(g_v);
    float* prkf = (float*)dev_ptr(g_rkf);
    bf16* pe_hi = (bf16*)dev_ptr(g_pe_hi);   bf16* pe_lo = (bf16*)dev_ptr(g_pe_lo);
    bf16* wrkT_hi = (bf16*)dev_ptr(g_wrkT_hi); bf16* wrkT_lo = (bf16*)dev_ptr(g_wrkT_lo);
    bf16* weT_hi = (bf16*)dev_ptr(g_weT_hi); bf16* weT_lo = (bf16*)dev_ptr(g_weT_lo);
    bf16* vT_hi = (bf16*)dev_ptr(g_vT_hi); bf16* vT_lo = (bf16*)dev_ptr(g_vT_lo);
    bf16* p_hi = (bf16*)dev_ptr(g_p_hi); bf16* p_lo = (bf16*)dev_ptr(g_p_lo);
    bf16* at_hi = (bf16*)dev_ptr(g_at_hi); bf16* at_lo = (bf16*)dev_ptr(g_at_lo);

    dim3 tb(32, 8);

    // 1: gamma features
    pf_gamma_raw_kernel<<<(RD * NB + 255) / 256, 256>>>();
    // 2: fused prep (input split + all weight transpose-splits)
    prep_kernel<<<8544, 256>>>(inputs, Wq, Wk, Wv, We, Wrk);
    // 3: gamma max
    pf_max_kernel<<<1, 1024>>>();
    // 4: fused V + QK projections (NT=128, 240 CTAs, forced 2 CTAs/SM) — ncu slot
    proj_gemm<<<240, 256, SM128>>>();
    // 5: positional feature build (needs gmax)
    pf_build_kernel<<<(RDP * 96 + 255) / 256, 256>>>();
    // 6: RK projection (K=192) -> head-major fp32
    mma_gemm<64, false><<<dim3(8, 24, 1), 256, SM64>>>(pe_hi, pe_lo, 0, wrkT_hi, wrkT_lo, 0,
        prkf, nullptr, nullptr, 0, 0, RDP, 192, 1.0f, nullptr, KD);
    // 7: fused glue: qw/qr (raw biases), k split, rk split
    fuse_split_kernel<<<(2 * QKSZ + RKSZ + 255) / 256, 256>>>(rwb, rrb);
    // 8: vT split
    tsplit_kernel<<<dim3(VD / 32, TT / 32, HH), tb>>>(pv, vT_hi, vT_lo, TT, VD,
        (size_t)TT * VD, (size_t)VD * TT);
    // 9: combined content + rel logits (K=64, 2400 CTAs, forced 2 CTAs/SM)
    logits_gemm<<<dim3(25, 12, HH), 256, SM128>>>();
    // 10: combine + softmax -> P (bf16 hi/lo)
    softmax_kernel<<<HH * TT, 256>>>();
    // 11: P @ V (K=1536) -> attn split bf16 directly
    mma_gemm<64, true><<<dim3(3, 12, HH), 256, SM64>>>(p_hi, p_lo, (size_t)TT * TT,
        vT_hi, vT_lo, (size_t)VD * TT, nullptr, at_hi, at_lo, CDIM, (size_t)VD,
        TT, TT, 1.0f, nullptr, 0);
    // 12: out = attn @ We + be (K=1536, NT=64)
    mma_gemm<64, false><<<dim3(24, 12, 1), 256, SM64>>>(at_hi, at_lo, 0, weT_hi, weT_lo, 0,
        out, nullptr, nullptr, CDIM, 0, TT, CDIM, 1.0f, be, 0);
}